// round 8
// baseline (speedup 1.0000x reference)
#include <cuda_runtime.h>
#include <cuda_fp16.h>
#include <cstdint>

#define NB 8
#define NT 1024
#define NC 512
#define NH 4
#define BT (NB*NT)          // 8192
#define NF 2048             // NH*NC

// ---------------- scratch (device globals) ----------------
__device__ __half g_h[BT * NC];                     // [bt][c]
__device__ __half g_qkT[(long long)4096 * BT];      // rows 0..2047 Q(h*512+c), 2048..4095 K ; [row][bt]
__device__ __half g_v2[(long long)BT * NF];         // [bt][h*512+d]
__device__ float  g_attn[32 * NC * NC];             // [b*4+h][c][d]  (fp32 logits)
__device__ __half g_attnh[32 * NC * NC];            // softmaxed, fp16
__device__ __half g_av2[(long long)BT * NF];        // [bt][h*512+c]
__device__ __half g_wqkT[6144 * NC];                // [row][c] row: sec*2048 + h*512 + c (sec 2 = V)
__device__ __half g_woutT[NC * NF];                 // [c][f]
__device__ float  g_mean[NB * 32];
__device__ float  g_rstd[NB * 32];

__device__ __forceinline__ uint32_t smem_u32(const void* p) {
    uint32_t a;
    asm("{ .reg .u64 t; cvta.to.shared.u64 t, %1; cvt.u32.u64 %0, t; }" : "=r"(a) : "l"(p));
    return a;
}
#define SWZ(o) ((o) ^ (((o) >> 3) & 0x70))

#define CPASYNC16(dst, src) \
    asm volatile("cp.async.cg.shared.global [%0], [%1], 16;" :: "r"(dst), "l"(src))
#define CP_COMMIT() asm volatile("cp.async.commit_group;" ::: "memory")
#define CP_WAIT2()  asm volatile("cp.async.wait_group 2;" ::: "memory")

#define LDSM4(r0, r1, r2, r3, addr) \
    asm volatile("ldmatrix.sync.aligned.m8n8.x4.shared.b16 {%0,%1,%2,%3}, [%4];" \
        : "=r"(r0), "=r"(r1), "=r"(r2), "=r"(r3) : "r"(addr))

// f16-accumulator MMA: first of chain takes zero-acc, rest chain in-place.
#define HMMA_F16_INIT(d, a0, a1, a2, a3, b0, b1) \
    asm volatile("mma.sync.aligned.m16n8k16.row.col.f16.f16.f16.f16 " \
        "{%0,%1}, {%2,%3,%4,%5}, {%6,%7}, {%8,%9};" \
        : "=r"((d)[0]), "=r"((d)[1]) \
        : "r"(a0), "r"(a1), "r"(a2), "r"(a3), "r"(b0), "r"(b1), "r"(0u), "r"(0u))

#define HMMA_F16(d, a0, a1, a2, a3, b0, b1) \
    asm volatile("mma.sync.aligned.m16n8k16.row.col.f16.f16.f16.f16 " \
        "{%0,%1}, {%2,%3,%4,%5}, {%6,%7}, {%0,%1};" \
        : "+r"((d)[0]), "+r"((d)[1]) \
        : "r"(a0), "r"(a1), "r"(a2), "r"(a3), "r"(b0), "r"(b1))

// ---------------- GroupNorm ----------------
__global__ void gn_stats(const float* __restrict__ x) {
    int bg = blockIdx.x;
    int b = bg >> 5, g = bg & 31;
    const float* base = x + (size_t)b * (NT * NC) + g * 16;
    float s = 0.f, ss = 0.f;
    for (int idx = threadIdx.x; idx < NT * 16; idx += 256) {
        float v = base[(idx >> 4) * NC + (idx & 15)];
        s += v; ss += v * v;
    }
    for (int o = 16; o; o >>= 1) {
        s  += __shfl_xor_sync(0xffffffffu, s,  o);
        ss += __shfl_xor_sync(0xffffffffu, ss, o);
    }
    __shared__ float sa[8], sb[8];
    int wid = threadIdx.x >> 5;
    if ((threadIdx.x & 31) == 0) { sa[wid] = s; sb[wid] = ss; }
    __syncthreads();
    if (threadIdx.x == 0) {
        float S = 0.f, SS = 0.f;
        #pragma unroll
        for (int i = 0; i < 8; i++) { S += sa[i]; SS += sb[i]; }
        float inv = 1.0f / (NT * 16);
        float mean = S * inv;
        float var  = SS * inv - mean * mean;
        g_mean[bg] = mean;
        g_rstd[bg] = rsqrtf(var + 1e-5f);
    }
}

__global__ void gn_apply(const float* __restrict__ x,
                         const float* __restrict__ scale,
                         const float* __restrict__ bias) {
    int idx = blockIdx.x * 256 + threadIdx.x;
    if (idx >= BT * NC) return;
    int c = idx & (NC - 1);
    int b = idx >> 19;
    int bg = b * 32 + (c >> 4);
    float v = (x[idx] - g_mean[bg]) * g_rstd[bg] * scale[c] + bias[c];
    g_h[idx] = __float2half(v);
}

// ---------------- weight transposes ----------------
__global__ void tr_wqkv(const float* __restrict__ w, __half* __restrict__ wT) {
    __shared__ float t[32][33];
    int blk = blockIdx.x;             // 0..191
    int sec = blk >> 6;
    int within = blk & 63;
    int h = within >> 4, ct = within & 15;
    int c0 = ct * 32;
    int fbase = h * 1536 + sec;
    int r0 = sec * 2048 + h * 512 + c0;
    int tx = threadIdx.x & 31, ty = threadIdx.x >> 5;
    for (int k0 = 0; k0 < 512; k0 += 32) {
        #pragma unroll
        for (int j = 0; j < 4; j++) {
            int k = ty + j * 8;
            t[k][tx] = w[(long long)(k0 + k) * 6144 + fbase + 3 * (c0 + tx)];
        }
        __syncthreads();
        #pragma unroll
        for (int j = 0; j < 4; j++) {
            int cc = ty + j * 8;
            wT[(long long)(r0 + cc) * 512 + k0 + tx] = __float2half(t[tx][cc]);
        }
        __syncthreads();
    }
}

__global__ void tr_wout(const float* __restrict__ w, __half* __restrict__ wT) {
    __shared__ float t[32][33];
    int f0 = blockIdx.x * 32, c0 = blockIdx.y * 32;
    int tx = threadIdx.x & 31, ty = threadIdx.x >> 5;
    #pragma unroll
    for (int j = 0; j < 4; j++)
        t[ty + j * 8][tx] = w[(long long)(f0 + ty + j * 8) * 512 + c0 + tx];
    __syncthreads();
    #pragma unroll
    for (int j = 0; j < 4; j++)
        wT[(long long)(c0 + ty + j * 8) * 2048 + f0 + tx] = __float2half(t[tx][ty + j * 8]);
}

// ---------------- softmax: fp32 in, fp16 out ----------------
__global__ void softmax512(const float* __restrict__ a, __half* __restrict__ o) {
    const float* row = a + (size_t)blockIdx.x * NC;
    __half* orow = o + (size_t)blockIdx.x * NC;
    int tid = threadIdx.x;
    float v0 = row[tid], v1 = row[tid + 256];
    float m = fmaxf(v0, v1);
    __shared__ float red[8];
    for (int off = 16; off; off >>= 1) m = fmaxf(m, __shfl_xor_sync(0xffffffffu, m, off));
    if ((tid & 31) == 0) red[tid >> 5] = m;
    __syncthreads();
    m = red[0];
    #pragma unroll
    for (int i = 1; i < 8; i++) m = fmaxf(m, red[i]);
    __syncthreads();
    float e0 = __expf(v0 - m), e1 = __expf(v1 - m);
    float s = e0 + e1;
    for (int off = 16; off; off >>= 1) s += __shfl_xor_sync(0xffffffffu, s, off);
    if ((tid & 31) == 0) red[tid >> 5] = s;
    __syncthreads();
    s = 0.f;
    #pragma unroll
    for (int i = 0; i < 8; i++) s += red[i];
    float inv = 1.0f / s;
    orow[tid] = __float2half(e0 * inv);
    orow[tid + 256] = __float2half(e1 * inv);
}

// ---------------- fp16 mma.sync GEMM (f16 acc, chunked f32 promote) ----------
// CTA 256x128, warp 64x64, BK=64, 4-stage cp.async. Within each K-block the
// accumulation runs in f16 (4 chained HMMAs, k=64); promoted into f32 at ks=3.

#define STAGEB 49152
#define NSTAGE 4
#define GSMEM (NSTAGE * STAGEB)

__device__ __forceinline__ int qkv_map_m(int r) {
    int sec = r >> 11, rem = r & 2047;
    return (rem >> 9) * 1536 + 3 * (rem & 511) + sec;
}
__device__ __forceinline__ int qkv_map_v(int n) {
    return (n >> 9) * 1536 + 3 * (n & 511) + 2;
}

__global__ void __launch_bounds__(256, 1)
hgemm(const __half* __restrict__ A, const __half* __restrict__ B, void* __restrict__ Cv,
      int K, int Asm, int Bsn, int Csm,
      int zInner, int Abi, int Abo, int Bbi, int Bbo,
      int Cbi, int Cbo, float alpha,
      const float* __restrict__ bias_m, const float* __restrict__ bias_n,
      const float* __restrict__ resid, int c16, int bmode) {
    extern __shared__ char smem[];
    uint32_t sbase = smem_u32(smem);
    int tid = threadIdx.x, lane = tid & 31, wid = tid >> 5;
    int g = lane >> 2, qid = lane & 3;
    int wm = (wid & 3) * 64, wn = (wid >> 2) * 64;

    int z = blockIdx.z;
    int zi = z % zInner, zo = z / zInner;
    A += (long long)zi * Abi + (long long)zo * Abo;
    B += (long long)zi * Bbi + (long long)zo * Bbo;
    long long cbase = (long long)zi * Cbi + (long long)zo * Cbo;
    int m0 = blockIdx.y * 256;
    int n0 = blockIdx.x * 128;
    A += (long long)m0 * Asm;
    B += (long long)n0 * Bsn;

    int row0 = tid >> 3, q0 = tid & 7;
    const __half* srcA = A + (long long)row0 * Asm + q0 * 8;
    const __half* srcB = B + (long long)row0 * Bsn + q0 * 8;
    uint32_t dstA = sbase + SWZ((uint32_t)(row0 * 128 + q0 * 16));
    uint32_t dstB = dstA + 32768;

    float acc[4][8][4];
    #pragma unroll
    for (int i = 0; i < 4; i++)
        #pragma unroll
        for (int j = 0; j < 8; j++)
            #pragma unroll
            for (int qq = 0; qq < 4; qq++) acc[i][j][qq] = 0.f;

    int KB = K >> 6;

    #pragma unroll
    for (int s = 0; s < 3; s++) {
        uint32_t so = s * STAGEB;
        #pragma unroll
        for (int t = 0; t < 8; t++)
            CPASYNC16(dstA + so + t * 4096, srcA + s * 64 + (long long)(32 * t) * Asm);
        #pragma unroll
        for (int t = 0; t < 4; t++)
            CPASYNC16(dstB + so + t * 4096, srcB + s * 64 + (long long)(32 * t) * Bsn);
        CP_COMMIT();
    }

    uint32_t baseA = (uint32_t)((wm + (lane & 15)) * 128 + (lane >> 4) * 16);
    uint32_t baseB = (uint32_t)((wn + (lane & 7) + ((lane >> 4) & 1) * 8) * 128 + ((lane >> 3) & 1) * 16);

    int st = 0;
    for (int kb = 0; kb < KB; kb++) {
        CP_WAIT2();
        __syncthreads();
        if (kb + 3 < KB) {
            int s3 = st + 3; if (s3 >= NSTAGE) s3 -= NSTAGE;
            uint32_t so = (uint32_t)s3 * STAGEB;
            #pragma unroll
            for (int t = 0; t < 8; t++)
                CPASYNC16(dstA + so + t * 4096, srcA + (kb + 3) * 64 + (long long)(32 * t) * Asm);
            #pragma unroll
            for (int t = 0; t < 4; t++)
                CPASYNC16(dstB + so + t * 4096, srcB + (kb + 3) * 64 + (long long)(32 * t) * Bsn);
        }
        CP_COMMIT();

        uint32_t sA = sbase + st * STAGEB;
        uint32_t sB = sA + 32768;

        uint32_t acc16[4][8][2];

        #pragma unroll
        for (int ks = 0; ks < 4; ks++) {
            uint32_t a[4][4], bf[4][4];
            #pragma unroll
            for (int mt = 0; mt < 4; mt++)
                LDSM4(a[mt][0], a[mt][1], a[mt][2], a[mt][3],
                      sA + SWZ(baseA + mt * 2048 + ks * 32));
            #pragma unroll
            for (int ntp = 0; ntp < 4; ntp++)
                LDSM4(bf[ntp][0], bf[ntp][1], bf[ntp][2], bf[ntp][3],
                      sB + SWZ(baseB + ntp * 2048 + ks * 32));
            #pragma unroll
            for (int mt = 0; mt < 4; mt++)
                #pragma unroll
                for (int nt = 0; nt < 8; nt++) {
                    uint32_t b0 = bf[nt >> 1][(nt & 1) * 2];
                    uint32_t b1 = bf[nt >> 1][(nt & 1) * 2 + 1];
                    if (ks == 0) {
                        HMMA_F16_INIT(acc16[mt][nt], a[mt][0], a[mt][1], a[mt][2], a[mt][3], b0, b1);
                    } else {
                        HMMA_F16(acc16[mt][nt], a[mt][0], a[mt][1], a[mt][2], a[mt][3], b0, b1);
                    }
                    if (ks == 3) {
                        uint32_t u0 = acc16[mt][nt][0], u1 = acc16[mt][nt][1];
                        float2 lo = __half22float2(*reinterpret_cast<__half2*>(&u0));
                        float2 hi = __half22float2(*reinterpret_cast<__half2*>(&u1));
                        acc[mt][nt][0] += lo.x; acc[mt][nt][1] += lo.y;
                        acc[mt][nt][2] += hi.x; acc[mt][nt][3] += hi.y;
                    }
                }
        }
        st++; if (st == NSTAGE) st = 0;
    }

    // ---------------- epilogue ----------------
    #pragma unroll
    for (int mt = 0; mt < 4; mt++) {
        int r = m0 + wm + 16 * mt + g;
        float bm0 = 0.f, bm1 = 0.f;
        if (bias_m) {
            if (bmode == 1) { bm0 = bias_m[qkv_map_m(r)]; bm1 = bias_m[qkv_map_m(r + 8)]; }
            else            { bm0 = bias_m[r]; bm1 = bias_m[r + 8]; }
        }
        #pragma unroll
        for (int nt = 0; nt < 8; nt++) {
            float* c = acc[mt][nt];
            int n = n0 + wn + 8 * nt + qid * 2;
            float bn0 = 0.f, bn1 = 0.f;
            if (bias_n) {
                if (bmode == 2) { bn0 = bias_n[qkv_map_v(n)]; bn1 = bias_n[qkv_map_v(n + 1)]; }
                else            { bn0 = bias_n[n]; bn1 = bias_n[n + 1]; }
            }
            float v00 = c[0] * alpha + bm0 + bn0;
            float v01 = c[1] * alpha + bm0 + bn1;
            float v10 = c[2] * alpha + bm1 + bn0;
            float v11 = c[3] * alpha + bm1 + bn1;
            long long o0 = cbase + (long long)r * Csm + n;
            long long o1 = cbase + (long long)(r + 8) * Csm + n;
            if (c16) {
                *(__half2*)((__half*)Cv + o0) = __floats2half2_rn(v00, v01);
                *(__half2*)((__half*)Cv + o1) = __floats2half2_rn(v10, v11);
            } else {
                float* C = (float*)Cv;
                if (resid) {
                    v00 += resid[o0]; v01 += resid[o0 + 1];
                    v10 += resid[o1]; v11 += resid[o1 + 1];
                }
                *(float2*)(C + o0) = make_float2(v00, v01);
                *(float2*)(C + o1) = make_float2(v10, v11);
            }
        }
    }
}

extern "C" void kernel_launch(void* const* d_in, const int* in_sizes, int n_in,
                              void* d_out, int out_size) {
    const float* x        = (const float*)d_in[0];
    const float* gn_scale = (const float*)d_in[1];
    const float* gn_bias  = (const float*)d_in[2];
    const float* w_qkv    = (const float*)d_in[3];
    const float* b_qkv    = (const float*)d_in[4];
    const float* w_out    = (const float*)d_in[5];
    const float* b_out    = (const float*)d_in[6];
    float* out = (float*)d_out;

    __half *h, *qkT, *v2, *attnh, *av2, *wqkT, *woutT;
    float *attn;
    cudaGetSymbolAddress((void**)&h,     g_h);
    cudaGetSymbolAddress((void**)&qkT,   g_qkT);
    cudaGetSymbolAddress((void**)&v2,    g_v2);
    cudaGetSymbolAddress((void**)&attn,  g_attn);
    cudaGetSymbolAddress((void**)&attnh, g_attnh);
    cudaGetSymbolAddress((void**)&av2,   g_av2);
    cudaGetSymbolAddress((void**)&wqkT,  g_wqkT);
    cudaGetSymbolAddress((void**)&woutT, g_woutT);

    cudaFuncSetAttribute(hgemm, cudaFuncAttributeMaxDynamicSharedMemorySize, GSMEM);

    gn_stats<<<NB * 32, 256>>>(x);                        // 0
    gn_apply<<<(BT * NC) / 256, 256>>>(x, gn_scale, gn_bias); // 1
    tr_wqkv<<<192, 256>>>(w_qkv, wqkT);                   // 2

    // 3: GEMM 2a: qkT[feat 0..4095][bt]  (m=feat, n=bt)
    hgemm<<<dim3(BT / 128, 4096 / 256, 1), 256, GSMEM>>>(
        wqkT, h, qkT, NC,
        512, 512, BT,
        1, 0, 0, 0, 0, 0, 0,
        1.0f, b_qkv, nullptr, nullptr, 1, 1);

    tr_wout<<<dim3(64, 16), 256>>>(w_out, woutT);         // 4

    // 5: GEMM 2b: v2[bt][f]  (m=bt, n=f; B = V-weight rows) — profiler target (-s 5)
    hgemm<<<dim3(NF / 128, BT / 256, 1), 256, GSMEM>>>(
        h, wqkT + 4096LL * 512, v2, NC,
        512, 512, NF,
        1, 0, 0, 0, 0, 0, 0,
        1.0f, nullptr, b_qkv, nullptr, 1, 2);

    // 6: GEMM 3: logits[z][c][d] = (1/32) Q·K ; z=b*4+h, fp32 out
    hgemm<<<dim3(NC / 128, NC / 256, 32), 256, GSMEM>>>(
        qkT, qkT + 2048LL * BT, attn, NT,
        BT, BT, NC,
        NH,
        512 * BT, NT, 512 * BT, NT,
        NC * NC, 4 * NC * NC,
        1.0f / 32.0f, nullptr, nullptr, nullptr, 0, 0);

    softmax512<<<32 * NC, 256>>>(attn, attnh);            // 7

    // 8: GEMM 5: av2[b*1024+t][h*512+c] = sum_d V[t,d]·P[c,d]  (m=t, n=c)
    hgemm<<<dim3(NC / 128, NT / 256, 32), 256, GSMEM>>>(
        v2, attnh, av2, NC,
        NF, NC, NF,
        NH,
        512, NT * NF,
        NC * NC, 4 * NC * NC,
        512, NT * NF,
        1.0f, nullptr, nullptr, nullptr, 1, 0);

    // 9: GEMM 6: out[b][t][c] = av2 @ woutT^T + b_out + x  (m=t, n=c, fp32+resid)
    hgemm<<<dim3(NC / 128, NT / 256, NB), 256, GSMEM>>>(
        av2, woutT, out, NF,
        NF, NF, NC,
        1,
        0, NT * NF, 0, 0,
        0, NT * NC,
        1.0f, nullptr, b_out, x, 0, 0);
}

// round 9
// speedup vs baseline: 1.1524x; 1.1524x over previous
#include <cuda_runtime.h>
#include <cuda_fp16.h>
#include <cstdint>

#define NB 8
#define NT 1024
#define NC 512
#define NH 4
#define BT (NB*NT)          // 8192
#define NF 2048             // NH*NC

// ---------------- scratch (device globals) ----------------
__device__ __half g_h[BT * NC];                     // [bt][c]
__device__ __half g_qkT[(long long)4096 * BT];      // rows 0..2047 Q(h*512+c), 2048..4095 K ; [row][bt]
__device__ __half g_v2[(long long)BT * NF];         // [bt][h*512+d]
__device__ __half g_attnh[32 * NC * NC];            // [b*4+h][c][d] logits -> softmaxed (fp16, in-place)
__device__ __half g_av2[(long long)BT * NF];        // [bt][h*512+c]
__device__ __half g_wqkT[6144 * NC];                // [row][c] row: sec*2048 + h*512 + c (sec 2 = V)
__device__ __half g_woutT[NC * NF];                 // [c][f]
__device__ float  g_mean[NB * 32];
__device__ float  g_rstd[NB * 32];

__device__ __forceinline__ uint32_t smem_u32(const void* p) {
    uint32_t a;
    asm("{ .reg .u64 t; cvta.to.shared.u64 t, %1; cvt.u32.u64 %0, t; }" : "=r"(a) : "l"(p));
    return a;
}
#define SWZ(o) ((o) ^ (((o) >> 3) & 0x70))

#define CPASYNC16(dst, src) \
    asm volatile("cp.async.cg.shared.global [%0], [%1], 16;" :: "r"(dst), "l"(src))
#define CP_COMMIT() asm volatile("cp.async.commit_group;" ::: "memory")
#define CP_WAIT2()  asm volatile("cp.async.wait_group 2;" ::: "memory")

#define LDSM4(r0, r1, r2, r3, addr) \
    asm volatile("ldmatrix.sync.aligned.m8n8.x4.shared.b16 {%0,%1,%2,%3}, [%4];" \
        : "=r"(r0), "=r"(r1), "=r"(r2), "=r"(r3) : "r"(addr))

#define HMMA16(d, a0, a1, a2, a3, b0, b1) \
    asm volatile("mma.sync.aligned.m16n8k16.row.col.f32.f16.f16.f32 " \
        "{%0,%1,%2,%3}, {%4,%5,%6,%7}, {%8,%9}, {%0,%1,%2,%3};" \
        : "+f"((d)[0]), "+f"((d)[1]), "+f"((d)[2]), "+f"((d)[3]) \
        : "r"(a0), "r"(a1), "r"(a2), "r"(a3), "r"(b0), "r"(b1))

// ---------------- GroupNorm ----------------
__global__ void gn_stats(const float* __restrict__ x) {
    int bg = blockIdx.x;
    int b = bg >> 5, g = bg & 31;
    const float* base = x + (size_t)b * (NT * NC) + g * 16;
    float s = 0.f, ss = 0.f;
    for (int idx = threadIdx.x; idx < NT * 16; idx += 256) {
        float v = base[(idx >> 4) * NC + (idx & 15)];
        s += v; ss += v * v;
    }
    for (int o = 16; o; o >>= 1) {
        s  += __shfl_xor_sync(0xffffffffu, s,  o);
        ss += __shfl_xor_sync(0xffffffffu, ss, o);
    }
    __shared__ float sa[8], sb[8];
    int wid = threadIdx.x >> 5;
    if ((threadIdx.x & 31) == 0) { sa[wid] = s; sb[wid] = ss; }
    __syncthreads();
    if (threadIdx.x == 0) {
        float S = 0.f, SS = 0.f;
        #pragma unroll
        for (int i = 0; i < 8; i++) { S += sa[i]; SS += sb[i]; }
        float inv = 1.0f / (NT * 16);
        float mean = S * inv;
        float var  = SS * inv - mean * mean;
        g_mean[bg] = mean;
        g_rstd[bg] = rsqrtf(var + 1e-5f);
    }
}

__global__ void gn_apply(const float* __restrict__ x,
                         const float* __restrict__ scale,
                         const float* __restrict__ bias) {
    int idx = blockIdx.x * 256 + threadIdx.x;
    if (idx >= BT * NC) return;
    int c = idx & (NC - 1);
    int b = idx >> 19;
    int bg = b * 32 + (c >> 4);
    float v = (x[idx] - g_mean[bg]) * g_rstd[bg] * scale[c] + bias[c];
    g_h[idx] = __float2half(v);
}

// ---------------- weight transposes ----------------
__global__ void tr_wqkv(const float* __restrict__ w, __half* __restrict__ wT) {
    __shared__ float t[32][33];
    int blk = blockIdx.x;             // 0..191
    int sec = blk >> 6;
    int within = blk & 63;
    int h = within >> 4, ct = within & 15;
    int c0 = ct * 32;
    int fbase = h * 1536 + sec;
    int r0 = sec * 2048 + h * 512 + c0;
    int tx = threadIdx.x & 31, ty = threadIdx.x >> 5;
    for (int k0 = 0; k0 < 512; k0 += 32) {
        #pragma unroll
        for (int j = 0; j < 4; j++) {
            int k = ty + j * 8;
            t[k][tx] = w[(long long)(k0 + k) * 6144 + fbase + 3 * (c0 + tx)];
        }
        __syncthreads();
        #pragma unroll
        for (int j = 0; j < 4; j++) {
            int cc = ty + j * 8;
            wT[(long long)(r0 + cc) * 512 + k0 + tx] = __float2half(t[tx][cc]);
        }
        __syncthreads();
    }
}

__global__ void tr_wout(const float* __restrict__ w, __half* __restrict__ wT) {
    __shared__ float t[32][33];
    int f0 = blockIdx.x * 32, c0 = blockIdx.y * 32;
    int tx = threadIdx.x & 31, ty = threadIdx.x >> 5;
    #pragma unroll
    for (int j = 0; j < 4; j++)
        t[ty + j * 8][tx] = w[(long long)(f0 + ty + j * 8) * 512 + c0 + tx];
    __syncthreads();
    #pragma unroll
    for (int j = 0; j < 4; j++)
        wT[(long long)(c0 + ty + j * 8) * 2048 + f0 + tx] = __float2half(t[tx][ty + j * 8]);
}

// ---------------- softmax over rows of 512, fp16 in-place ----------------
__global__ void softmax512(__half* __restrict__ a) {
    __half* row = a + (size_t)blockIdx.x * NC;
    int tid = threadIdx.x;
    float v0 = __half2float(row[tid]), v1 = __half2float(row[tid + 256]);
    float m = fmaxf(v0, v1);
    __shared__ float red[8];
    for (int off = 16; off; off >>= 1) m = fmaxf(m, __shfl_xor_sync(0xffffffffu, m, off));
    if ((tid & 31) == 0) red[tid >> 5] = m;
    __syncthreads();
    m = red[0];
    #pragma unroll
    for (int i = 1; i < 8; i++) m = fmaxf(m, red[i]);
    __syncthreads();
    float e0 = __expf(v0 - m), e1 = __expf(v1 - m);
    float s = e0 + e1;
    for (int off = 16; off; off >>= 1) s += __shfl_xor_sync(0xffffffffu, s, off);
    if ((tid & 31) == 0) red[tid >> 5] = s;
    __syncthreads();
    s = 0.f;
    #pragma unroll
    for (int i = 0; i < 8; i++) s += red[i];
    float inv = 1.0f / s;
    row[tid] = __float2half(e0 * inv);
    row[tid + 256] = __float2half(e1 * inv);
}

// ---------------- fp16 mma.sync GEMM: CTA 256x128, warp 64x64, BK=64 ----------
// 4-stage cp.async + FRAGMENT DOUBLE BUFFERING: ldmatrix for ks+1 issues before
// the HMMAs of ks, so LSU/crossbar overlaps the tensor pipe.

#define STAGEB 49152
#define NSTAGE 4
#define GSMEM (NSTAGE * STAGEB)

__device__ __forceinline__ int qkv_map_m(int r) {
    int sec = r >> 11, rem = r & 2047;
    return (rem >> 9) * 1536 + 3 * (rem & 511) + sec;
}
__device__ __forceinline__ int qkv_map_v(int n) {
    return (n >> 9) * 1536 + 3 * (n & 511) + 2;
}

#define LOAD_FRAGS(bb, ks) do { \
    _Pragma("unroll") \
    for (int mt = 0; mt < 4; mt++) \
        LDSM4(afr[bb][mt][0], afr[bb][mt][1], afr[bb][mt][2], afr[bb][mt][3], \
              sA + SWZ(baseA + mt * 2048 + (ks) * 32)); \
    _Pragma("unroll") \
    for (int ntp = 0; ntp < 4; ntp++) \
        LDSM4(bfr[bb][ntp][0], bfr[bb][ntp][1], bfr[bb][ntp][2], bfr[bb][ntp][3], \
              sB + SWZ(baseB + ntp * 2048 + (ks) * 32)); \
} while (0)

__global__ void __launch_bounds__(256, 1)
hgemm(const __half* __restrict__ A, const __half* __restrict__ B, void* __restrict__ Cv,
      int K, int Asm, int Bsn, int Csm,
      int zInner, int Abi, int Abo, int Bbi, int Bbo,
      int Cbi, int Cbo, float alpha,
      const float* __restrict__ bias_m, const float* __restrict__ bias_n,
      const float* __restrict__ resid, int c16, int bmode) {
    extern __shared__ char smem[];
    uint32_t sbase = smem_u32(smem);
    int tid = threadIdx.x, lane = tid & 31, wid = tid >> 5;
    int g = lane >> 2, qid = lane & 3;
    int wm = (wid & 3) * 64, wn = (wid >> 2) * 64;

    int z = blockIdx.z;
    int zi = z % zInner, zo = z / zInner;
    A += (long long)zi * Abi + (long long)zo * Abo;
    B += (long long)zi * Bbi + (long long)zo * Bbo;
    long long cbase = (long long)zi * Cbi + (long long)zo * Cbo;
    int m0 = blockIdx.y * 256;
    int n0 = blockIdx.x * 128;
    A += (long long)m0 * Asm;
    B += (long long)n0 * Bsn;

    int row0 = tid >> 3, q0 = tid & 7;
    const __half* srcA = A + (long long)row0 * Asm + q0 * 8;
    const __half* srcB = B + (long long)row0 * Bsn + q0 * 8;
    uint32_t dstA = sbase + SWZ((uint32_t)(row0 * 128 + q0 * 16));
    uint32_t dstB = dstA + 32768;

    float acc[4][8][4];
    #pragma unroll
    for (int i = 0; i < 4; i++)
        #pragma unroll
        for (int j = 0; j < 8; j++)
            #pragma unroll
            for (int qq = 0; qq < 4; qq++) acc[i][j][qq] = 0.f;

    int KB = K >> 6;

    #pragma unroll
    for (int s = 0; s < 3; s++) {
        uint32_t so = s * STAGEB;
        #pragma unroll
        for (int t = 0; t < 8; t++)
            CPASYNC16(dstA + so + t * 4096, srcA + s * 64 + (long long)(32 * t) * Asm);
        #pragma unroll
        for (int t = 0; t < 4; t++)
            CPASYNC16(dstB + so + t * 4096, srcB + s * 64 + (long long)(32 * t) * Bsn);
        CP_COMMIT();
    }

    uint32_t baseA = (uint32_t)((wm + (lane & 15)) * 128 + (lane >> 4) * 16);
    uint32_t baseB = (uint32_t)((wn + (lane & 7) + ((lane >> 4) & 1) * 8) * 128 + ((lane >> 3) & 1) * 16);

    int st = 0;
    for (int kb = 0; kb < KB; kb++) {
        CP_WAIT2();
        __syncthreads();
        if (kb + 3 < KB) {
            int s3 = st + 3; if (s3 >= NSTAGE) s3 -= NSTAGE;
            uint32_t so = (uint32_t)s3 * STAGEB;
            #pragma unroll
            for (int t = 0; t < 8; t++)
                CPASYNC16(dstA + so + t * 4096, srcA + (kb + 3) * 64 + (long long)(32 * t) * Asm);
            #pragma unroll
            for (int t = 0; t < 4; t++)
                CPASYNC16(dstB + so + t * 4096, srcB + (kb + 3) * 64 + (long long)(32 * t) * Bsn);
        }
        CP_COMMIT();

        uint32_t sA = sbase + st * STAGEB;
        uint32_t sB = sA + 32768;

        uint32_t afr[2][4][4], bfr[2][4][4];
        LOAD_FRAGS(0, 0);

        #pragma unroll
        for (int ks = 0; ks < 4; ks++) {
            int cur = ks & 1;
            if (ks < 3) LOAD_FRAGS(cur ^ 1, ks + 1);   // overlap with HMMAs below
            #pragma unroll
            for (int mt = 0; mt < 4; mt++)
                #pragma unroll
                for (int nt = 0; nt < 8; nt++) {
                    uint32_t b0 = bfr[cur][nt >> 1][(nt & 1) * 2];
                    uint32_t b1 = bfr[cur][nt >> 1][(nt & 1) * 2 + 1];
                    HMMA16(acc[mt][nt], afr[cur][mt][0], afr[cur][mt][1],
                           afr[cur][mt][2], afr[cur][mt][3], b0, b1);
                }
        }
        st++; if (st == NSTAGE) st = 0;
    }

    // ---------------- epilogue ----------------
    #pragma unroll
    for (int mt = 0; mt < 4; mt++) {
        int r = m0 + wm + 16 * mt + g;
        float bm0 = 0.f, bm1 = 0.f;
        if (bias_m) {
            if (bmode == 1) { bm0 = bias_m[qkv_map_m(r)]; bm1 = bias_m[qkv_map_m(r + 8)]; }
            else            { bm0 = bias_m[r]; bm1 = bias_m[r + 8]; }
        }
        #pragma unroll
        for (int nt = 0; nt < 8; nt++) {
            float* c = acc[mt][nt];
            int n = n0 + wn + 8 * nt + qid * 2;
            float bn0 = 0.f, bn1 = 0.f;
            if (bias_n) {
                if (bmode == 2) { bn0 = bias_n[qkv_map_v(n)]; bn1 = bias_n[qkv_map_v(n + 1)]; }
                else            { bn0 = bias_n[n]; bn1 = bias_n[n + 1]; }
            }
            float v00 = c[0] * alpha + bm0 + bn0;
            float v01 = c[1] * alpha + bm0 + bn1;
            float v10 = c[2] * alpha + bm1 + bn0;
            float v11 = c[3] * alpha + bm1 + bn1;
            long long o0 = cbase + (long long)r * Csm + n;
            long long o1 = cbase + (long long)(r + 8) * Csm + n;
            if (c16) {
                *(__half2*)((__half*)Cv + o0) = __floats2half2_rn(v00, v01);
                *(__half2*)((__half*)Cv + o1) = __floats2half2_rn(v10, v11);
            } else {
                float* C = (float*)Cv;
                if (resid) {
                    v00 += resid[o0]; v01 += resid[o0 + 1];
                    v10 += resid[o1]; v11 += resid[o1 + 1];
                }
                *(float2*)(C + o0) = make_float2(v00, v01);
                *(float2*)(C + o1) = make_float2(v10, v11);
            }
        }
    }
}

extern "C" void kernel_launch(void* const* d_in, const int* in_sizes, int n_in,
                              void* d_out, int out_size) {
    const float* x        = (const float*)d_in[0];
    const float* gn_scale = (const float*)d_in[1];
    const float* gn_bias  = (const float*)d_in[2];
    const float* w_qkv    = (const float*)d_in[3];
    const float* b_qkv    = (const float*)d_in[4];
    const float* w_out    = (const float*)d_in[5];
    const float* b_out    = (const float*)d_in[6];
    float* out = (float*)d_out;

    __half *h, *qkT, *v2, *attnh, *av2, *wqkT, *woutT;
    cudaGetSymbolAddress((void**)&h,     g_h);
    cudaGetSymbolAddress((void**)&qkT,   g_qkT);
    cudaGetSymbolAddress((void**)&v2,    g_v2);
    cudaGetSymbolAddress((void**)&attnh, g_attnh);
    cudaGetSymbolAddress((void**)&av2,   g_av2);
    cudaGetSymbolAddress((void**)&wqkT,  g_wqkT);
    cudaGetSymbolAddress((void**)&woutT, g_woutT);

    cudaFuncSetAttribute(hgemm, cudaFuncAttributeMaxDynamicSharedMemorySize, GSMEM);

    gn_stats<<<NB * 32, 256>>>(x);                        // 0
    gn_apply<<<(BT * NC) / 256, 256>>>(x, gn_scale, gn_bias); // 1
    tr_wqkv<<<192, 256>>>(w_qkv, wqkT);                   // 2

    // 3: GEMM 2a: qkT[feat 0..4095][bt]  (m=feat, n=bt)
    hgemm<<<dim3(BT / 128, 4096 / 256, 1), 256, GSMEM>>>(
        wqkT, h, qkT, NC,
        512, 512, BT,
        1, 0, 0, 0, 0, 0, 0,
        1.0f, b_qkv, nullptr, nullptr, 1, 1);

    tr_wout<<<dim3(64, 16), 256>>>(w_out, woutT);         // 4

    // 5: GEMM 2b: v2[bt][f]  (m=bt, n=f; B = V-weight rows) — profiler target (-s 5)
    hgemm<<<dim3(NF / 128, BT / 256, 1), 256, GSMEM>>>(
        h, wqkT + 4096LL * 512, v2, NC,
        512, 512, NF,
        1, 0, 0, 0, 0, 0, 0,
        1.0f, nullptr, b_qkv, nullptr, 1, 2);

    // 6: GEMM 3: logits[z][c][d] = (1/32) Q·K ; z=b*4+h, fp16 out
    hgemm<<<dim3(NC / 128, NC / 256, 32), 256, GSMEM>>>(
        qkT, qkT + 2048LL * BT, attnh, NT,
        BT, BT, NC,
        NH,
        512 * BT, NT, 512 * BT, NT,
        NC * NC, 4 * NC * NC,
        1.0f / 32.0f, nullptr, nullptr, nullptr, 1, 0);

    softmax512<<<32 * NC, 256>>>(attnh);                  // 7

    // 8: GEMM 5: av2[b*1024+t][h*512+c] = sum_d V[t,d]·P[c,d]  (m=t, n=c)
    hgemm<<<dim3(NC / 128, NT / 256, 32), 256, GSMEM>>>(
        v2, attnh, av2, NC,
        NF, NC, NF,
        NH,
        512, NT * NF,
        NC * NC, 4 * NC * NC,
        512, NT * NF,
        1.0f, nullptr, nullptr, nullptr, 1, 0);

    // 9: GEMM 6: out[b][t][c] = av2 @ woutT^T + b_out + x  (m=t, n=c, fp32+resid)
    hgemm<<<dim3(NC / 128, NT / 256, NB), 256, GSMEM>>>(
        av2, woutT, out, NF,
        NF, NF, NC,
        1,
        0, NT * NF, 0, 0,
        0, NT * NC,
        1.0f, nullptr, b_out, x, 0, 0);
}

// round 10
// speedup vs baseline: 1.2067x; 1.0471x over previous
#include <cuda_runtime.h>
#include <cuda_fp16.h>
#include <cstdint>

#define NB 8
#define NT 1024
#define NC 512
#define NH 4
#define BT (NB*NT)          // 8192
#define NF 2048             // NH*NC

// ---------------- scratch (device globals) ----------------
__device__ __half g_h[BT * NC];                     // [bt][c]
__device__ __half g_qkT[(long long)4096 * BT];      // rows 0..2047 Q(h*512+c), 2048..4095 K ; [row][bt]
__device__ __half g_v2[(long long)BT * NF];         // [bt][h*512+d]
__device__ __half g_attnh[32 * NC * NC];            // [b*4+h][c][d] logits -> softmax (fp16, in place)
__device__ __half g_av2[(long long)BT * NF];        // [bt][h*512+c]
__device__ __half g_wqkT[6144 * NC];                // [row][c] row: sec*2048 + h*512 + c (sec 2 = V)
__device__ __half g_woutT[NC * NF];                 // [c][f]
__device__ float  g_mean[NB * 32];
__device__ float  g_rstd[NB * 32];

__device__ __forceinline__ uint32_t smem_u32(const void* p) {
    uint32_t a;
    asm("{ .reg .u64 t; cvta.to.shared.u64 t, %1; cvt.u32.u64 %0, t; }" : "=r"(a) : "l"(p));
    return a;
}
#define SWZ(o) ((o) ^ (((o) >> 3) & 0x70))

#define CPASYNC16(dst, src) \
    asm volatile("cp.async.cg.shared.global [%0], [%1], 16;" :: "r"(dst), "l"(src))
#define CP_COMMIT() asm volatile("cp.async.commit_group;" ::: "memory")
#define CP_WAIT1()  asm volatile("cp.async.wait_group 1;" ::: "memory")

#define LDSM4(r0, r1, r2, r3, addr) \
    asm volatile("ldmatrix.sync.aligned.m8n8.x4.shared.b16 {%0,%1,%2,%3}, [%4];" \
        : "=r"(r0), "=r"(r1), "=r"(r2), "=r"(r3) : "r"(addr))

#define HMMA16(d, a0, a1, a2, a3, b0, b1) \
    asm volatile("mma.sync.aligned.m16n8k16.row.col.f32.f16.f16.f32 " \
        "{%0,%1,%2,%3}, {%4,%5,%6,%7}, {%8,%9}, {%0,%1,%2,%3};" \
        : "+f"((d)[0]), "+f"((d)[1]), "+f"((d)[2]), "+f"((d)[3]) \
        : "r"(a0), "r"(a1), "r"(a2), "r"(a3), "r"(b0), "r"(b1))

// ---------------- GroupNorm ----------------
__global__ void gn_stats(const float* __restrict__ x) {
    int bg = blockIdx.x;
    int b = bg >> 5, g = bg & 31;
    const float* base = x + (size_t)b * (NT * NC) + g * 16;
    float s = 0.f, ss = 0.f;
    for (int idx = threadIdx.x; idx < NT * 16; idx += 256) {
        float v = base[(idx >> 4) * NC + (idx & 15)];
        s += v; ss += v * v;
    }
    for (int o = 16; o; o >>= 1) {
        s  += __shfl_xor_sync(0xffffffffu, s,  o);
        ss += __shfl_xor_sync(0xffffffffu, ss, o);
    }
    __shared__ float sa[8], sb[8];
    int wid = threadIdx.x >> 5;
    if ((threadIdx.x & 31) == 0) { sa[wid] = s; sb[wid] = ss; }
    __syncthreads();
    if (threadIdx.x == 0) {
        float S = 0.f, SS = 0.f;
        #pragma unroll
        for (int i = 0; i < 8; i++) { S += sa[i]; SS += sb[i]; }
        float inv = 1.0f / (NT * 16);
        float mean = S * inv;
        float var  = SS * inv - mean * mean;
        g_mean[bg] = mean;
        g_rstd[bg] = rsqrtf(var + 1e-5f);
    }
}

__global__ void gn_apply(const float* __restrict__ x,
                         const float* __restrict__ scale,
                         const float* __restrict__ bias) {
    int idx = blockIdx.x * 256 + threadIdx.x;
    if (idx >= BT * NC) return;
    int c = idx & (NC - 1);
    int b = idx >> 19;
    int bg = b * 32 + (c >> 4);
    float v = (x[idx] - g_mean[bg]) * g_rstd[bg] * scale[c] + bias[c];
    g_h[idx] = __float2half(v);
}

// ---------------- weight transposes ----------------
__global__ void tr_wqkv(const float* __restrict__ w, __half* __restrict__ wT) {
    __shared__ float t[32][33];
    int blk = blockIdx.x;             // 0..191
    int sec = blk >> 6;
    int within = blk & 63;
    int h = within >> 4, ct = within & 15;
    int c0 = ct * 32;
    int fbase = h * 1536 + sec;
    int r0 = sec * 2048 + h * 512 + c0;
    int tx = threadIdx.x & 31, ty = threadIdx.x >> 5;
    for (int k0 = 0; k0 < 512; k0 += 32) {
        #pragma unroll
        for (int j = 0; j < 4; j++) {
            int k = ty + j * 8;
            t[k][tx] = w[(long long)(k0 + k) * 6144 + fbase + 3 * (c0 + tx)];
        }
        __syncthreads();
        #pragma unroll
        for (int j = 0; j < 4; j++) {
            int cc = ty + j * 8;
            wT[(long long)(r0 + cc) * 512 + k0 + tx] = __float2half(t[tx][cc]);
        }
        __syncthreads();
    }
}

__global__ void tr_wout(const float* __restrict__ w, __half* __restrict__ wT) {
    __shared__ float t[32][33];
    int f0 = blockIdx.x * 32, c0 = blockIdx.y * 32;
    int tx = threadIdx.x & 31, ty = threadIdx.x >> 5;
    #pragma unroll
    for (int j = 0; j < 4; j++)
        t[ty + j * 8][tx] = w[(long long)(f0 + ty + j * 8) * 512 + c0 + tx];
    __syncthreads();
    #pragma unroll
    for (int j = 0; j < 4; j++)
        wT[(long long)(c0 + ty + j * 8) * 2048 + f0 + tx] = __float2half(t[tx][ty + j * 8]);
}

// ---------------- softmax over rows of 512, fp16 in-place ----------------
__global__ void softmax512(__half* __restrict__ a) {
    __half* row = a + (size_t)blockIdx.x * NC;
    int tid = threadIdx.x;
    float v0 = __half2float(row[tid]), v1 = __half2float(row[tid + 256]);
    float m = fmaxf(v0, v1);
    __shared__ float red[8];
    for (int off = 16; off; off >>= 1) m = fmaxf(m, __shfl_xor_sync(0xffffffffu, m, off));
    if ((tid & 31) == 0) red[tid >> 5] = m;
    __syncthreads();
    m = red[0];
    #pragma unroll
    for (int i = 1; i < 8; i++) m = fmaxf(m, red[i]);
    __syncthreads();
    float e0 = __expf(v0 - m), e1 = __expf(v1 - m);
    float s = e0 + e1;
    for (int off = 16; off; off >>= 1) s += __shfl_xor_sync(0xffffffffu, s, off);
    if ((tid & 31) == 0) red[tid >> 5] = s;
    __syncthreads();
    s = 0.f;
    #pragma unroll
    for (int i = 0; i < 8; i++) s += red[i];
    float inv = 1.0f / s;
    row[tid] = __float2half(e0 * inv);
    row[tid + 256] = __float2half(e1 * inv);
}

// ---------------- fp16 mma.sync GEMM: CTA 128x128, warp 64x32, BK=64 ----------
// 3-stage cp.async, 2 CTAs/SM (best-measured config, R5), fused bias remaps.

#define STAGEB 32768
#define NSTAGE 3
#define GSMEM (NSTAGE * STAGEB)

__device__ __forceinline__ int qkv_map_m(int r) {
    int sec = r >> 11, rem = r & 2047;
    return (rem >> 9) * 1536 + 3 * (rem & 511) + sec;
}
__device__ __forceinline__ int qkv_map_v(int n) {
    return (n >> 9) * 1536 + 3 * (n & 511) + 2;
}

__global__ void __launch_bounds__(256, 2)
hgemm(const __half* __restrict__ A, const __half* __restrict__ B, void* __restrict__ Cv,
      int K, int Asm, int Bsn, int Csm,
      int zInner, int Abi, int Abo, int Bbi, int Bbo,
      int Cbi, int Cbo, float alpha,
      const float* __restrict__ bias_m, const float* __restrict__ bias_n,
      const float* __restrict__ resid, int c16, int bmode) {
    extern __shared__ char smem[];
    uint32_t sbase = smem_u32(smem);
    int tid = threadIdx.x, lane = tid & 31, wid = tid >> 5;
    int g = lane >> 2, qid = lane & 3;
    int wm = (wid & 1) * 64, wn = (wid >> 1) * 32;

    int z = blockIdx.z;
    int zi = z % zInner, zo = z / zInner;
    A += (long long)zi * Abi + (long long)zo * Abo;
    B += (long long)zi * Bbi + (long long)zo * Bbo;
    long long cbase = (long long)zi * Cbi + (long long)zo * Cbo;
    int m0 = blockIdx.y * 128;
    int n0 = blockIdx.x * 128;
    A += (long long)m0 * Asm;
    B += (long long)n0 * Bsn;

    // cp.async mapping: 1024 16B-chunks per 16KB tile; 4 per thread per tile
    int row0 = tid >> 3, q0 = tid & 7;
    const __half* srcA = A + (long long)row0 * Asm + q0 * 8;
    const __half* srcB = B + (long long)row0 * Bsn + q0 * 8;
    uint32_t dstA = sbase + SWZ((uint32_t)(row0 * 128 + q0 * 16));

    float acc[4][4][4];
    #pragma unroll
    for (int i = 0; i < 4; i++)
        #pragma unroll
        for (int j = 0; j < 4; j++)
            #pragma unroll
            for (int qq = 0; qq < 4; qq++) acc[i][j][qq] = 0.f;

    int KB = K >> 6;

    #pragma unroll
    for (int s = 0; s < 2; s++) {
        uint32_t so = s * STAGEB;
        #pragma unroll
        for (int t = 0; t < 4; t++) {
            CPASYNC16(dstA + so + t * 4096,         srcA + s * 64 + (long long)(32 * t) * Asm);
            CPASYNC16(dstA + so + 16384 + t * 4096, srcB + s * 64 + (long long)(32 * t) * Bsn);
        }
        CP_COMMIT();
    }

    uint32_t baseA = (uint32_t)((wm + (lane & 15)) * 128 + (lane >> 4) * 16);
    uint32_t baseB = (uint32_t)((wn + (lane & 7) + ((lane >> 4) & 1) * 8) * 128 + ((lane >> 3) & 1) * 16);

    int st = 0;
    for (int kb = 0; kb < KB; kb++) {
        CP_WAIT1();
        __syncthreads();
        if (kb + 2 < KB) {
            int s2 = st + 2; if (s2 >= NSTAGE) s2 -= NSTAGE;
            uint32_t so = (uint32_t)s2 * STAGEB;
            #pragma unroll
            for (int t = 0; t < 4; t++) {
                CPASYNC16(dstA + so + t * 4096,         srcA + (kb + 2) * 64 + (long long)(32 * t) * Asm);
                CPASYNC16(dstA + so + 16384 + t * 4096, srcB + (kb + 2) * 64 + (long long)(32 * t) * Bsn);
            }
        }
        CP_COMMIT();

        uint32_t sA = sbase + st * STAGEB;
        uint32_t sB = sA + 16384;

        #pragma unroll
        for (int ks = 0; ks < 4; ks++) {
            uint32_t a[4][4], bf[2][4];
            #pragma unroll
            for (int mt = 0; mt < 4; mt++)
                LDSM4(a[mt][0], a[mt][1], a[mt][2], a[mt][3],
                      sA + SWZ(baseA + mt * 2048 + ks * 32));
            #pragma unroll
            for (int ntp = 0; ntp < 2; ntp++)
                LDSM4(bf[ntp][0], bf[ntp][1], bf[ntp][2], bf[ntp][3],
                      sB + SWZ(baseB + ntp * 2048 + ks * 32));
            #pragma unroll
            for (int mt = 0; mt < 4; mt++)
                #pragma unroll
                for (int nt = 0; nt < 4; nt++) {
                    uint32_t b0 = bf[nt >> 1][(nt & 1) * 2];
                    uint32_t b1 = bf[nt >> 1][(nt & 1) * 2 + 1];
                    HMMA16(acc[mt][nt], a[mt][0], a[mt][1], a[mt][2], a[mt][3], b0, b1);
                }
        }
        st++; if (st == NSTAGE) st = 0;
    }

    // ---------------- epilogue ----------------
    #pragma unroll
    for (int mt = 0; mt < 4; mt++) {
        int r = m0 + wm + 16 * mt + g;
        float bm0 = 0.f, bm1 = 0.f;
        if (bias_m) {
            if (bmode == 1) { bm0 = bias_m[qkv_map_m(r)]; bm1 = bias_m[qkv_map_m(r + 8)]; }
            else            { bm0 = bias_m[r]; bm1 = bias_m[r + 8]; }
        }
        #pragma unroll
        for (int nt = 0; nt < 4; nt++) {
            float* c = acc[mt][nt];
            int n = n0 + wn + 8 * nt + qid * 2;
            float bn0 = 0.f, bn1 = 0.f;
            if (bias_n) {
                if (bmode == 2) { bn0 = bias_n[qkv_map_v(n)]; bn1 = bias_n[qkv_map_v(n + 1)]; }
                else            { bn0 = bias_n[n]; bn1 = bias_n[n + 1]; }
            }
            float v00 = c[0] * alpha + bm0 + bn0;
            float v01 = c[1] * alpha + bm0 + bn1;
            float v10 = c[2] * alpha + bm1 + bn0;
            float v11 = c[3] * alpha + bm1 + bn1;
            long long o0 = cbase + (long long)r * Csm + n;
            long long o1 = cbase + (long long)(r + 8) * Csm + n;
            if (c16) {
                *(__half2*)((__half*)Cv + o0) = __floats2half2_rn(v00, v01);
                *(__half2*)((__half*)Cv + o1) = __floats2half2_rn(v10, v11);
            } else {
                float* C = (float*)Cv;
                if (resid) {
                    v00 += resid[o0]; v01 += resid[o0 + 1];
                    v10 += resid[o1]; v11 += resid[o1 + 1];
                }
                *(float2*)(C + o0) = make_float2(v00, v01);
                *(float2*)(C + o1) = make_float2(v10, v11);
            }
        }
    }
}

extern "C" void kernel_launch(void* const* d_in, const int* in_sizes, int n_in,
                              void* d_out, int out_size) {
    const float* x        = (const float*)d_in[0];
    const float* gn_scale = (const float*)d_in[1];
    const float* gn_bias  = (const float*)d_in[2];
    const float* w_qkv    = (const float*)d_in[3];
    const float* b_qkv    = (const float*)d_in[4];
    const float* w_out    = (const float*)d_in[5];
    const float* b_out    = (const float*)d_in[6];
    float* out = (float*)d_out;

    __half *h, *qkT, *v2, *attnh, *av2, *wqkT, *woutT;
    cudaGetSymbolAddress((void**)&h,     g_h);
    cudaGetSymbolAddress((void**)&qkT,   g_qkT);
    cudaGetSymbolAddress((void**)&v2,    g_v2);
    cudaGetSymbolAddress((void**)&attnh, g_attnh);
    cudaGetSymbolAddress((void**)&av2,   g_av2);
    cudaGetSymbolAddress((void**)&wqkT,  g_wqkT);
    cudaGetSymbolAddress((void**)&woutT, g_woutT);

    cudaFuncSetAttribute(hgemm, cudaFuncAttributeMaxDynamicSharedMemorySize, GSMEM);

    gn_stats<<<NB * 32, 256>>>(x);
    gn_apply<<<(BT * NC) / 256, 256>>>(x, gn_scale, gn_bias);
    tr_wqkv<<<192, 256>>>(w_qkv, wqkT);

    // GEMM 2a: qkT[feat 0..4095][bt]  (m=feat, n=bt)
    hgemm<<<dim3(BT / 128, 4096 / 128, 1), 256, GSMEM>>>(
        wqkT, h, qkT, NC,
        512, 512, BT,
        1, 0, 0, 0, 0, 0, 0,
        1.0f, b_qkv, nullptr, nullptr, 1, 1);

    tr_wout<<<dim3(64, 16), 256>>>(w_out, woutT);

    // GEMM 2b: v2[bt][f]  (m=bt, n=f; B = V-weight rows)
    hgemm<<<dim3(NF / 128, BT / 128, 1), 256, GSMEM>>>(
        h, wqkT + 4096LL * 512, v2, NC,
        512, 512, NF,
        1, 0, 0, 0, 0, 0, 0,
        1.0f, nullptr, b_qkv, nullptr, 1, 2);

    // GEMM 3: logits[z][c][d] = (1/32) Q·K ; z=b*4+h, fp16 out
    hgemm<<<dim3(NC / 128, NC / 128, 32), 256, GSMEM>>>(
        qkT, qkT + 2048LL * BT, attnh, NT,
        BT, BT, NC,
        NH,
        512 * BT, NT, 512 * BT, NT,
        NC * NC, 4 * NC * NC,
        1.0f / 32.0f, nullptr, nullptr, nullptr, 1, 0);

    softmax512<<<32 * NC, 256>>>(attnh);

    // GEMM 5: av2[b*1024+t][h*512+c] = sum_d V[t,d]·P[c,d]  (m=t, n=c)
    hgemm<<<dim3(NC / 128, NT / 128, 32), 256, GSMEM>>>(
        v2, attnh, av2, NC,
        NF, NC, NF,
        NH,
        512, NT * NF,
        NC * NC, 4 * NC * NC,
        512, NT * NF,
        1.0f, nullptr, nullptr, nullptr, 1, 0);

    // GEMM 6: out[b][t][c] = av2 @ woutT^T + b_out + x  (m=t, n=c, fp32+resid)
    hgemm<<<dim3(NC / 128, NT / 128, NB), 256, GSMEM>>>(
        av2, woutT, out, NF,
        NF, NF, NC,
        1,
        0, NT * NF, 0, 0,
        0, NT * NC,
        1.0f, nullptr, b_out, x, 0, 0);
}

// round 11
// speedup vs baseline: 1.2345x; 1.0230x over previous
#include <cuda_runtime.h>
#include <cuda_fp16.h>
#include <cstdint>

#define NB 8
#define NT 1024
#define NC 512
#define NH 4
#define BT (NB*NT)          // 8192
#define NF 2048             // NH*NC

// ---------------- scratch (device globals) ----------------
__device__ __half g_h[BT * NC];                     // [bt][c]
__device__ __half g_qkT[(long long)4096 * BT];      // rows 0..2047 Q(h*512+c), 2048..4095 K ; [row][bt]
__device__ __half g_v2[(long long)BT * NF];         // [bt][h*512+d]
__device__ __half g_attnh[32 * NC * NC];            // [b*4+h][c][d] logits -> softmax (fp16, in place)
__device__ __half g_av2[(long long)BT * NF];        // [bt][h*512+c]
__device__ __half g_wqkT[6144 * NC];                // [row][c] row: sec*2048 + h*512 + c (sec 2 = V)
__device__ __half g_woutT[NC * NF];                 // [c][f]

__device__ __forceinline__ uint32_t smem_u32(const void* p) {
    uint32_t a;
    asm("{ .reg .u64 t; cvta.to.shared.u64 t, %1; cvt.u32.u64 %0, t; }" : "=r"(a) : "l"(p));
    return a;
}
#define SWZ(o) ((o) ^ (((o) >> 3) & 0x70))

#define CPASYNC16(dst, src) \
    asm volatile("cp.async.cg.shared.global [%0], [%1], 16;" :: "r"(dst), "l"(src))
#define CP_COMMIT() asm volatile("cp.async.commit_group;" ::: "memory")
#define CP_WAIT1()  asm volatile("cp.async.wait_group 1;" ::: "memory")

#define LDSM4(r0, r1, r2, r3, addr) \
    asm volatile("ldmatrix.sync.aligned.m8n8.x4.shared.b16 {%0,%1,%2,%3}, [%4];" \
        : "=r"(r0), "=r"(r1), "=r"(r2), "=r"(r3) : "r"(addr))

#define HMMA16(d, a0, a1, a2, a3, b0, b1) \
    asm volatile("mma.sync.aligned.m16n8k16.row.col.f32.f16.f16.f32 " \
        "{%0,%1,%2,%3}, {%4,%5,%6,%7}, {%8,%9}, {%0,%1,%2,%3};" \
        : "+f"((d)[0]), "+f"((d)[1]), "+f"((d)[2]), "+f"((d)[3]) \
        : "r"(a0), "r"(a1), "r"(a2), "r"(a3), "r"(b0), "r"(b1))

// ---------------- fused GroupNorm: one block per (b, group) ----------------
__global__ void gn_fused(const float* __restrict__ x,
                         const float* __restrict__ scale,
                         const float* __restrict__ bias) {
    int bg = blockIdx.x;                 // 0..255
    int b = bg >> 5, g = bg & 31;
    const float* base = x + (size_t)b * (NT * NC) + g * 16;
    __half* hbase = g_h + (size_t)b * (NT * NC) + g * 16;
    int tid = threadIdx.x;
    int col = tid & 15;                  // invariant across the strided loop (256 % 16 == 0)
    float sc = scale[g * 16 + col];
    float bi = bias[g * 16 + col];

    float s = 0.f, ss = 0.f;
    for (int idx = tid; idx < NT * 16; idx += 256) {
        float v = base[(idx >> 4) * NC + (idx & 15)];
        s += v; ss += v * v;
    }
    for (int o = 16; o; o >>= 1) {
        s  += __shfl_xor_sync(0xffffffffu, s,  o);
        ss += __shfl_xor_sync(0xffffffffu, ss, o);
    }
    __shared__ float sa[8], sb[8];
    __shared__ float s_mean, s_rstd;
    int wid = tid >> 5;
    if ((tid & 31) == 0) { sa[wid] = s; sb[wid] = ss; }
    __syncthreads();
    if (tid == 0) {
        float S = 0.f, SS = 0.f;
        #pragma unroll
        for (int i = 0; i < 8; i++) { S += sa[i]; SS += sb[i]; }
        float inv = 1.0f / (NT * 16);
        float mean = S * inv;
        float var  = SS * inv - mean * mean;
        s_mean = mean;
        s_rstd = rsqrtf(var + 1e-5f);
    }
    __syncthreads();
    float mean = s_mean, rstd = s_rstd;
    for (int idx = tid; idx < NT * 16; idx += 256) {
        int off = (idx >> 4) * NC + (idx & 15);
        hbase[off] = __float2half((base[off] - mean) * rstd * sc + bi);
    }
}

// ---------------- merged weight transposes ----------------
// blocks [0,192): w_qkv -> wqkT ; blocks [192, 192+1024): w_out -> woutT
__global__ void tr_all(const float* __restrict__ wqkv, const float* __restrict__ wout) {
    __shared__ float t[32][33];
    int blk = blockIdx.x;
    int tx = threadIdx.x & 31, ty = threadIdx.x >> 5;
    if (blk < 192) {
        int sec = blk >> 6;
        int within = blk & 63;
        int h = within >> 4, ct = within & 15;
        int c0 = ct * 32;
        int fbase = h * 1536 + sec;
        int r0 = sec * 2048 + h * 512 + c0;
        for (int k0 = 0; k0 < 512; k0 += 32) {
            #pragma unroll
            for (int j = 0; j < 4; j++) {
                int k = ty + j * 8;
                t[k][tx] = wqkv[(long long)(k0 + k) * 6144 + fbase + 3 * (c0 + tx)];
            }
            __syncthreads();
            #pragma unroll
            for (int j = 0; j < 4; j++) {
                int cc = ty + j * 8;
                g_wqkT[(long long)(r0 + cc) * 512 + k0 + tx] = __float2half(t[tx][cc]);
            }
            __syncthreads();
        }
    } else {
        int q = blk - 192;                 // 0..1023
        int f0 = (q & 63) * 32, c0 = (q >> 6) * 32;
        #pragma unroll
        for (int j = 0; j < 4; j++)
            t[ty + j * 8][tx] = wout[(long long)(f0 + ty + j * 8) * 512 + c0 + tx];
        __syncthreads();
        #pragma unroll
        for (int j = 0; j < 4; j++)
            g_woutT[(long long)(c0 + ty + j * 8) * 2048 + f0 + tx] = __float2half(t[tx][ty + j * 8]);
    }
}

// ---------------- softmax over rows of 512, fp16 in-place ----------------
__global__ void softmax512(__half* __restrict__ a) {
    __half* row = a + (size_t)blockIdx.x * NC;
    int tid = threadIdx.x;
    float v0 = __half2float(row[tid]), v1 = __half2float(row[tid + 256]);
    float m = fmaxf(v0, v1);
    __shared__ float red[8];
    for (int off = 16; off; off >>= 1) m = fmaxf(m, __shfl_xor_sync(0xffffffffu, m, off));
    if ((tid & 31) == 0) red[tid >> 5] = m;
    __syncthreads();
    m = red[0];
    #pragma unroll
    for (int i = 1; i < 8; i++) m = fmaxf(m, red[i]);
    __syncthreads();
    float e0 = __expf(v0 - m), e1 = __expf(v1 - m);
    float s = e0 + e1;
    for (int off = 16; off; off >>= 1) s += __shfl_xor_sync(0xffffffffu, s, off);
    if ((tid & 31) == 0) red[tid >> 5] = s;
    __syncthreads();
    s = 0.f;
    #pragma unroll
    for (int i = 0; i < 8; i++) s += red[i];
    float inv = 1.0f / s;
    row[tid] = __float2half(e0 * inv);
    row[tid + 256] = __float2half(e1 * inv);
}

// ---------------- fp16 mma.sync GEMM: CTA 128x128, warp 64x32, BK=64 ----------
// 3-stage cp.async, 2 CTAs/SM, fused bias remaps. (Best-measured config.)

#define STAGEB 32768
#define NSTAGE 3
#define GSMEM (NSTAGE * STAGEB)

__device__ __forceinline__ int qkv_map_m(int r) {
    int sec = r >> 11, rem = r & 2047;
    return (rem >> 9) * 1536 + 3 * (rem & 511) + sec;
}
__device__ __forceinline__ int qkv_map_v(int n) {
    return (n >> 9) * 1536 + 3 * (n & 511) + 2;
}

__global__ void __launch_bounds__(256, 2)
hgemm(const __half* __restrict__ A, const __half* __restrict__ B, void* __restrict__ Cv,
      int K, int Asm, int Bsn, int Csm,
      int zInner, int Abi, int Abo, int Bbi, int Bbo,
      int Cbi, int Cbo, float alpha,
      const float* __restrict__ bias_m, const float* __restrict__ bias_n,
      const float* __restrict__ resid, int c16, int bmode) {
    extern __shared__ char smem[];
    uint32_t sbase = smem_u32(smem);
    int tid = threadIdx.x, lane = tid & 31, wid = tid >> 5;
    int g = lane >> 2, qid = lane & 3;
    int wm = (wid & 1) * 64, wn = (wid >> 1) * 32;

    int z = blockIdx.z;
    int zi = z % zInner, zo = z / zInner;
    A += (long long)zi * Abi + (long long)zo * Abo;
    B += (long long)zi * Bbi + (long long)zo * Bbo;
    long long cbase = (long long)zi * Cbi + (long long)zo * Cbo;
    int m0 = blockIdx.y * 128;
    int n0 = blockIdx.x * 128;
    A += (long long)m0 * Asm;
    B += (long long)n0 * Bsn;

    int row0 = tid >> 3, q0 = tid & 7;
    const __half* srcA = A + (long long)row0 * Asm + q0 * 8;
    const __half* srcB = B + (long long)row0 * Bsn + q0 * 8;
    uint32_t dstA = sbase + SWZ((uint32_t)(row0 * 128 + q0 * 16));

    float acc[4][4][4];
    #pragma unroll
    for (int i = 0; i < 4; i++)
        #pragma unroll
        for (int j = 0; j < 4; j++)
            #pragma unroll
            for (int qq = 0; qq < 4; qq++) acc[i][j][qq] = 0.f;

    int KB = K >> 6;

    #pragma unroll
    for (int s = 0; s < 2; s++) {
        uint32_t so = s * STAGEB;
        #pragma unroll
        for (int t = 0; t < 4; t++) {
            CPASYNC16(dstA + so + t * 4096,         srcA + s * 64 + (long long)(32 * t) * Asm);
            CPASYNC16(dstA + so + 16384 + t * 4096, srcB + s * 64 + (long long)(32 * t) * Bsn);
        }
        CP_COMMIT();
    }

    uint32_t baseA = (uint32_t)((wm + (lane & 15)) * 128 + (lane >> 4) * 16);
    uint32_t baseB = (uint32_t)((wn + (lane & 7) + ((lane >> 4) & 1) * 8) * 128 + ((lane >> 3) & 1) * 16);

    int st = 0;
    for (int kb = 0; kb < KB; kb++) {
        CP_WAIT1();
        __syncthreads();
        if (kb + 2 < KB) {
            int s2 = st + 2; if (s2 >= NSTAGE) s2 -= NSTAGE;
            uint32_t so = (uint32_t)s2 * STAGEB;
            #pragma unroll
            for (int t = 0; t < 4; t++) {
                CPASYNC16(dstA + so + t * 4096,         srcA + (kb + 2) * 64 + (long long)(32 * t) * Asm);
                CPASYNC16(dstA + so + 16384 + t * 4096, srcB + (kb + 2) * 64 + (long long)(32 * t) * Bsn);
            }
        }
        CP_COMMIT();

        uint32_t sA = sbase + st * STAGEB;
        uint32_t sB = sA + 16384;

        #pragma unroll
        for (int ks = 0; ks < 4; ks++) {
            uint32_t a[4][4], bf[2][4];
            #pragma unroll
            for (int mt = 0; mt < 4; mt++)
                LDSM4(a[mt][0], a[mt][1], a[mt][2], a[mt][3],
                      sA + SWZ(baseA + mt * 2048 + ks * 32));
            #pragma unroll
            for (int ntp = 0; ntp < 2; ntp++)
                LDSM4(bf[ntp][0], bf[ntp][1], bf[ntp][2], bf[ntp][3],
                      sB + SWZ(baseB + ntp * 2048 + ks * 32));
            #pragma unroll
            for (int mt = 0; mt < 4; mt++)
                #pragma unroll
                for (int nt = 0; nt < 4; nt++) {
                    uint32_t b0 = bf[nt >> 1][(nt & 1) * 2];
                    uint32_t b1 = bf[nt >> 1][(nt & 1) * 2 + 1];
                    HMMA16(acc[mt][nt], a[mt][0], a[mt][1], a[mt][2], a[mt][3], b0, b1);
                }
        }
        st++; if (st == NSTAGE) st = 0;
    }

    // ---------------- epilogue ----------------
    #pragma unroll
    for (int mt = 0; mt < 4; mt++) {
        int r = m0 + wm + 16 * mt + g;
        float bm0 = 0.f, bm1 = 0.f;
        if (bias_m) {
            if (bmode == 1) { bm0 = bias_m[qkv_map_m(r)]; bm1 = bias_m[qkv_map_m(r + 8)]; }
            else            { bm0 = bias_m[r]; bm1 = bias_m[r + 8]; }
        }
        #pragma unroll
        for (int nt = 0; nt < 4; nt++) {
            float* c = acc[mt][nt];
            int n = n0 + wn + 8 * nt + qid * 2;
            float bn0 = 0.f, bn1 = 0.f;
            if (bias_n) {
                if (bmode == 2) { bn0 = bias_n[qkv_map_v(n)]; bn1 = bias_n[qkv_map_v(n + 1)]; }
                else            { bn0 = bias_n[n]; bn1 = bias_n[n + 1]; }
            }
            float v00 = c[0] * alpha + bm0 + bn0;
            float v01 = c[1] * alpha + bm0 + bn1;
            float v10 = c[2] * alpha + bm1 + bn0;
            float v11 = c[3] * alpha + bm1 + bn1;
            long long o0 = cbase + (long long)r * Csm + n;
            long long o1 = cbase + (long long)(r + 8) * Csm + n;
            if (c16) {
                *(__half2*)((__half*)Cv + o0) = __floats2half2_rn(v00, v01);
                *(__half2*)((__half*)Cv + o1) = __floats2half2_rn(v10, v11);
            } else {
                float* C = (float*)Cv;
                if (resid) {
                    v00 += resid[o0]; v01 += resid[o0 + 1];
                    v10 += resid[o1]; v11 += resid[o1 + 1];
                }
                *(float2*)(C + o0) = make_float2(v00, v01);
                *(float2*)(C + o1) = make_float2(v10, v11);
            }
        }
    }
}

extern "C" void kernel_launch(void* const* d_in, const int* in_sizes, int n_in,
                              void* d_out, int out_size) {
    const float* x        = (const float*)d_in[0];
    const float* gn_scale = (const float*)d_in[1];
    const float* gn_bias  = (const float*)d_in[2];
    const float* w_qkv    = (const float*)d_in[3];
    const float* b_qkv    = (const float*)d_in[4];
    const float* w_out    = (const float*)d_in[5];
    const float* b_out    = (const float*)d_in[6];
    float* out = (float*)d_out;

    __half *h, *qkT, *v2, *attnh, *av2, *wqkT, *woutT;
    cudaGetSymbolAddress((void**)&h,     g_h);
    cudaGetSymbolAddress((void**)&qkT,   g_qkT);
    cudaGetSymbolAddress((void**)&v2,    g_v2);
    cudaGetSymbolAddress((void**)&attnh, g_attnh);
    cudaGetSymbolAddress((void**)&av2,   g_av2);
    cudaGetSymbolAddress((void**)&wqkT,  g_wqkT);
    cudaGetSymbolAddress((void**)&woutT, g_woutT);

    cudaFuncSetAttribute(hgemm, cudaFuncAttributeMaxDynamicSharedMemorySize, GSMEM);

    // 0: fused groupnorm (stats + apply)
    gn_fused<<<NB * 32, 256>>>(x, gn_scale, gn_bias);
    // 1: merged weight transposes
    tr_all<<<192 + 1024, 256>>>(w_qkv, w_out);

    // 2: GEMM 2a: qkT[feat 0..4095][bt]  (m=feat, n=bt)
    hgemm<<<dim3(BT / 128, 4096 / 128, 1), 256, GSMEM>>>(
        wqkT, h, qkT, NC,
        512, 512, BT,
        1, 0, 0, 0, 0, 0, 0,
        1.0f, b_qkv, nullptr, nullptr, 1, 1);

    // 3: GEMM 2b: v2[bt][f]  (m=bt, n=f; B = V-weight rows)
    hgemm<<<dim3(NF / 128, BT / 128, 1), 256, GSMEM>>>(
        h, wqkT + 4096LL * 512, v2, NC,
        512, 512, NF,
        1, 0, 0, 0, 0, 0, 0,
        1.0f, nullptr, b_qkv, nullptr, 1, 2);

    // 4: GEMM 3: logits[z][c][d] = (1/32) Q·K ; z=b*4+h, fp16 out
    hgemm<<<dim3(NC / 128, NC / 128, 32), 256, GSMEM>>>(
        qkT, qkT + 2048LL * BT, attnh, NT,
        BT, BT, NC,
        NH,
        512 * BT, NT, 512 * BT, NT,
        NC * NC, 4 * NC * NC,
        1.0f / 32.0f, nullptr, nullptr, nullptr, 1, 0);

    // 5: softmax over d (fp16 in-place)
    softmax512<<<32 * NC, 256>>>(attnh);

    // 6: GEMM 5: av2[b*1024+t][h*512+c] = sum_d V[t,d]·P[c,d]  (m=t, n=c)
    hgemm<<<dim3(NC / 128, NT / 128, 32), 256, GSMEM>>>(
        v2, attnh, av2, NC,
        NF, NC, NF,
        NH,
        512, NT * NF,
        NC * NC, 4 * NC * NC,
        512, NT * NF,
        1.0f, nullptr, nullptr, nullptr, 1, 0);

    // 7: GEMM 6: out[b][t][c] = av2 @ woutT^T + b_out + x  (m=t, n=c, fp32+resid)
    hgemm<<<dim3(NC / 128, NT / 128, NB), 256, GSMEM>>>(
        av2, woutT, out, NF,
        NF, NF, NC,
        1,
        0, NT * NF, 0, 0,
        0, NT * NC,
        1.0f, nullptr, b_out, x, 0, 0);
}

// round 12
// speedup vs baseline: 1.2676x; 1.0268x over previous
#include <cuda_runtime.h>
#include <cuda_fp16.h>
#include <cstdint>

#define NB 8
#define NT 1024
#define NC 512
#define NH 4
#define BT (NB*NT)          // 8192
#define NF 2048             // NH*NC

// ---------------- scratch (device globals) ----------------
__device__ __half g_h[BT * NC];                     // [bt][c]
__device__ __half g_qkT[(long long)4096 * BT];      // rows 0..2047 Q(h*512+c), 2048..4095 K ; [row][bt]
__device__ __half g_v2[(long long)BT * NF];         // [bt][h*512+d]
__device__ __half g_attnh[32 * NC * NC];            // [z][c][d]: logits -> E=exp(l-2) in place
__device__ float  g_Z[32 * NC];                     // row sums of E
__device__ __half g_av2[(long long)BT * NF];        // [bt][h*512+c]
__device__ __half g_wqkT[6144 * NC];                // [row][c] row: sec*2048 + h*512 + c (sec 2 = V)
__device__ __half g_woutT[NC * NF];                 // [c][f]

__device__ __forceinline__ uint32_t smem_u32(const void* p) {
    uint32_t a;
    asm("{ .reg .u64 t; cvta.to.shared.u64 t, %1; cvt.u32.u64 %0, t; }" : "=r"(a) : "l"(p));
    return a;
}
#define SWZ(o) ((o) ^ (((o) >> 3) & 0x70))

#define CPASYNC16(dst, src) \
    asm volatile("cp.async.cg.shared.global [%0], [%1], 16;" :: "r"(dst), "l"(src))
#define CP_COMMIT() asm volatile("cp.async.commit_group;" ::: "memory")
#define CP_WAIT1()  asm volatile("cp.async.wait_group 1;" ::: "memory")

#define LDSM4(r0, r1, r2, r3, addr) \
    asm volatile("ldmatrix.sync.aligned.m8n8.x4.shared.b16 {%0,%1,%2,%3}, [%4];" \
        : "=r"(r0), "=r"(r1), "=r"(r2), "=r"(r3) : "r"(addr))

#define HMMA16(d, a0, a1, a2, a3, b0, b1) \
    asm volatile("mma.sync.aligned.m16n8k16.row.col.f32.f16.f16.f32 " \
        "{%0,%1,%2,%3}, {%4,%5,%6,%7}, {%8,%9}, {%0,%1,%2,%3};" \
        : "+f"((d)[0]), "+f"((d)[1]), "+f"((d)[2]), "+f"((d)[3]) \
        : "r"(a0), "r"(a1), "r"(a2), "r"(a3), "r"(b0), "r"(b1))

// ---------------- fused GroupNorm: one block per (b, group) ----------------
__global__ void gn_fused(const float* __restrict__ x,
                         const float* __restrict__ scale,
                         const float* __restrict__ bias) {
    int bg = blockIdx.x;                 // 0..255
    int b = bg >> 5, g = bg & 31;
    const float* base = x + (size_t)b * (NT * NC) + g * 16;
    __half* hbase = g_h + (size_t)b * (NT * NC) + g * 16;
    int tid = threadIdx.x;
    int col = tid & 15;
    float sc = scale[g * 16 + col];
    float bi = bias[g * 16 + col];

    float s = 0.f, ss = 0.f;
    for (int idx = tid; idx < NT * 16; idx += 256) {
        float v = base[(idx >> 4) * NC + (idx & 15)];
        s += v; ss += v * v;
    }
    for (int o = 16; o; o >>= 1) {
        s  += __shfl_xor_sync(0xffffffffu, s,  o);
        ss += __shfl_xor_sync(0xffffffffu, ss, o);
    }
    __shared__ float sa[8], sb[8];
    __shared__ float s_mean, s_rstd;
    int wid = tid >> 5;
    if ((tid & 31) == 0) { sa[wid] = s; sb[wid] = ss; }
    __syncthreads();
    if (tid == 0) {
        float S = 0.f, SS = 0.f;
        #pragma unroll
        for (int i = 0; i < 8; i++) { S += sa[i]; SS += sb[i]; }
        float inv = 1.0f / (NT * 16);
        float mean = S * inv;
        float var  = SS * inv - mean * mean;
        s_mean = mean;
        s_rstd = rsqrtf(var + 1e-5f);
    }
    __syncthreads();
    float mean = s_mean, rstd = s_rstd;
    for (int idx = tid; idx < NT * 16; idx += 256) {
        int off = (idx >> 4) * NC + (idx & 15);
        hbase[off] = __float2half((base[off] - mean) * rstd * sc + bi);
    }
}

// ---------------- merged weight transposes ----------------
__global__ void tr_all(const float* __restrict__ wqkv, const float* __restrict__ wout) {
    __shared__ float t[32][33];
    int blk = blockIdx.x;
    int tx = threadIdx.x & 31, ty = threadIdx.x >> 5;
    if (blk < 192) {
        int sec = blk >> 6;
        int within = blk & 63;
        int h = within >> 4, ct = within & 15;
        int c0 = ct * 32;
        int fbase = h * 1536 + sec;
        int r0 = sec * 2048 + h * 512 + c0;
        for (int k0 = 0; k0 < 512; k0 += 32) {
            #pragma unroll
            for (int j = 0; j < 4; j++) {
                int k = ty + j * 8;
                t[k][tx] = wqkv[(long long)(k0 + k) * 6144 + fbase + 3 * (c0 + tx)];
            }
            __syncthreads();
            #pragma unroll
            for (int j = 0; j < 4; j++) {
                int cc = ty + j * 8;
                g_wqkT[(long long)(r0 + cc) * 512 + k0 + tx] = __float2half(t[tx][cc]);
            }
            __syncthreads();
        }
    } else {
        int q = blk - 192;                 // 0..1023
        int f0 = (q & 63) * 32, c0 = (q >> 6) * 32;
        #pragma unroll
        for (int j = 0; j < 4; j++)
            t[ty + j * 8][tx] = wout[(long long)(f0 + ty + j * 8) * 512 + c0 + tx];
        __syncthreads();
        #pragma unroll
        for (int j = 0; j < 4; j++)
            g_woutT[(long long)(c0 + ty + j * 8) * 2048 + f0 + tx] = __float2half(t[tx][ty + j * 8]);
    }
}

// ---------------- exp + row-sum over rows of 512 (fp16 in place, Z fp32) -------
// logits are O(1) (normalized inputs, /32); exp(l-2) cannot overflow fp16.
__global__ void softexp512(__half* __restrict__ a, float* __restrict__ Z) {
    __half* row = a + (size_t)blockIdx.x * NC;
    int tid = threadIdx.x;
    float v0 = __half2float(row[tid]), v1 = __half2float(row[tid + 256]);
    float e0 = __expf(v0 - 2.0f), e1 = __expf(v1 - 2.0f);
    float s = e0 + e1;
    __shared__ float red[8];
    for (int off = 16; off; off >>= 1) s += __shfl_xor_sync(0xffffffffu, s, off);
    if ((tid & 31) == 0) red[tid >> 5] = s;
    __syncthreads();
    row[tid] = __float2half(e0);
    row[tid + 256] = __float2half(e1);
    if (tid == 0) {
        float S = 0.f;
        #pragma unroll
        for (int i = 0; i < 8; i++) S += red[i];
        Z[blockIdx.x] = 1.0f / S;       // store reciprocal
    }
}

// ---------------- fp16 mma.sync GEMM body: CTA 128x128, warp 64x32, BK=64 ------
#define STAGEB 32768
#define NSTAGE 3
#define GSMEM (NSTAGE * STAGEB)

__device__ __forceinline__ int qkv_map_m(int r) {
    int sec = r >> 11, rem = r & 2047;
    return (rem >> 9) * 1536 + 3 * (rem & 511) + sec;
}
__device__ __forceinline__ int qkv_map_v(int n) {
    return (n >> 9) * 1536 + 3 * (n & 511) + 2;
}

__device__ __forceinline__ void gemm_body(
        char* smem,
        const __half* __restrict__ A, const __half* __restrict__ B, void* __restrict__ Cv,
        int K, int Asm, int Bsn, int Csm, long long cbase, int m0, int n0,
        float alpha,
        const float* __restrict__ bias_m, const float* __restrict__ bias_n,
        const float* __restrict__ resid, int c16, int bmode,
        const float* __restrict__ rowscale, long long rsbase) {
    uint32_t sbase = smem_u32(smem);
    int tid = threadIdx.x, lane = tid & 31, wid = tid >> 5;
    int g = lane >> 2, qid = lane & 3;
    int wm = (wid & 1) * 64, wn = (wid >> 1) * 32;

    A += (long long)m0 * Asm;
    B += (long long)n0 * Bsn;

    int row0 = tid >> 3, q0 = tid & 7;
    const __half* srcA = A + (long long)row0 * Asm + q0 * 8;
    const __half* srcB = B + (long long)row0 * Bsn + q0 * 8;
    uint32_t dstA = sbase + SWZ((uint32_t)(row0 * 128 + q0 * 16));

    float acc[4][4][4];
    #pragma unroll
    for (int i = 0; i < 4; i++)
        #pragma unroll
        for (int j = 0; j < 4; j++)
            #pragma unroll
            for (int qq = 0; qq < 4; qq++) acc[i][j][qq] = 0.f;

    int KB = K >> 6;

    #pragma unroll
    for (int s = 0; s < 2; s++) {
        uint32_t so = s * STAGEB;
        #pragma unroll
        for (int t = 0; t < 4; t++) {
            CPASYNC16(dstA + so + t * 4096,         srcA + s * 64 + (long long)(32 * t) * Asm);
            CPASYNC16(dstA + so + 16384 + t * 4096, srcB + s * 64 + (long long)(32 * t) * Bsn);
        }
        CP_COMMIT();
    }

    uint32_t baseA = (uint32_t)((wm + (lane & 15)) * 128 + (lane >> 4) * 16);
    uint32_t baseB = (uint32_t)((wn + (lane & 7) + ((lane >> 4) & 1) * 8) * 128 + ((lane >> 3) & 1) * 16);

    int st = 0;
    for (int kb = 0; kb < KB; kb++) {
        CP_WAIT1();
        __syncthreads();
        if (kb + 2 < KB) {
            int s2 = st + 2; if (s2 >= NSTAGE) s2 -= NSTAGE;
            uint32_t so = (uint32_t)s2 * STAGEB;
            #pragma unroll
            for (int t = 0; t < 4; t++) {
                CPASYNC16(dstA + so + t * 4096,         srcA + (kb + 2) * 64 + (long long)(32 * t) * Asm);
                CPASYNC16(dstA + so + 16384 + t * 4096, srcB + (kb + 2) * 64 + (long long)(32 * t) * Bsn);
            }
        }
        CP_COMMIT();

        uint32_t sA = sbase + st * STAGEB;
        uint32_t sB = sA + 16384;

        #pragma unroll
        for (int ks = 0; ks < 4; ks++) {
            uint32_t a[4][4], bf[2][4];
            #pragma unroll
            for (int mt = 0; mt < 4; mt++)
                LDSM4(a[mt][0], a[mt][1], a[mt][2], a[mt][3],
                      sA + SWZ(baseA + mt * 2048 + ks * 32));
            #pragma unroll
            for (int ntp = 0; ntp < 2; ntp++)
                LDSM4(bf[ntp][0], bf[ntp][1], bf[ntp][2], bf[ntp][3],
                      sB + SWZ(baseB + ntp * 2048 + ks * 32));
            #pragma unroll
            for (int mt = 0; mt < 4; mt++)
                #pragma unroll
                for (int nt = 0; nt < 4; nt++) {
                    uint32_t b0 = bf[nt >> 1][(nt & 1) * 2];
                    uint32_t b1 = bf[nt >> 1][(nt & 1) * 2 + 1];
                    HMMA16(acc[mt][nt], a[mt][0], a[mt][1], a[mt][2], a[mt][3], b0, b1);
                }
        }
        st++; if (st == NSTAGE) st = 0;
    }

    // ---------------- epilogue ----------------
    #pragma unroll
    for (int mt = 0; mt < 4; mt++) {
        int r = m0 + wm + 16 * mt + g;
        float bm0 = 0.f, bm1 = 0.f;
        if (bias_m) {
            if (bmode == 1) { bm0 = bias_m[qkv_map_m(r)]; bm1 = bias_m[qkv_map_m(r + 8)]; }
            else            { bm0 = bias_m[r]; bm1 = bias_m[r + 8]; }
        }
        #pragma unroll
        for (int nt = 0; nt < 4; nt++) {
            float* c = acc[mt][nt];
            int n = n0 + wn + 8 * nt + qid * 2;
            float bn0 = 0.f, bn1 = 0.f;
            if (bias_n) {
                if (bmode == 2) { bn0 = bias_n[qkv_map_v(n)]; bn1 = bias_n[qkv_map_v(n + 1)]; }
                else            { bn0 = bias_n[n]; bn1 = bias_n[n + 1]; }
            }
            float v00 = c[0] * alpha + bm0 + bn0;
            float v01 = c[1] * alpha + bm0 + bn1;
            float v10 = c[2] * alpha + bm1 + bn0;
            float v11 = c[3] * alpha + bm1 + bn1;
            if (rowscale) {
                float rs0 = rowscale[rsbase + n];
                float rs1 = rowscale[rsbase + n + 1];
                v00 *= rs0; v01 *= rs1; v10 *= rs0; v11 *= rs1;
            }
            long long o0 = cbase + (long long)r * Csm + n;
            long long o1 = cbase + (long long)(r + 8) * Csm + n;
            if (c16) {
                *(__half2*)((__half*)Cv + o0) = __floats2half2_rn(v00, v01);
                *(__half2*)((__half*)Cv + o1) = __floats2half2_rn(v10, v11);
            } else {
                float* C = (float*)Cv;
                if (resid) {
                    v00 += resid[o0]; v01 += resid[o0 + 1];
                    v10 += resid[o1]; v11 += resid[o1 + 1];
                }
                *(float2*)(C + o0) = make_float2(v00, v01);
                *(float2*)(C + o1) = make_float2(v10, v11);
            }
        }
    }
}

// generic batched wrapper
__global__ void __launch_bounds__(256, 2)
hgemm(const __half* __restrict__ A, const __half* __restrict__ B, void* __restrict__ Cv,
      int K, int Asm, int Bsn, int Csm,
      int zInner, int Abi, int Abo, int Bbi, int Bbo,
      int Cbi, int Cbo, float alpha,
      const float* __restrict__ bias_m, const float* __restrict__ bias_n,
      const float* __restrict__ resid, int c16, int bmode,
      const float* __restrict__ rowscale) {
    extern __shared__ char smem[];
    int z = blockIdx.z;
    int zi = z % zInner, zo = z / zInner;
    gemm_body(smem,
              A + (long long)zi * Abi + (long long)zo * Abo,
              B + (long long)zi * Bbi + (long long)zo * Bbo,
              Cv, K, Asm, Bsn, Csm,
              (long long)zi * Cbi + (long long)zo * Cbo,
              blockIdx.y * 128, blockIdx.x * 128,
              alpha, bias_m, bias_n, resid, c16, bmode,
              rowscale, (long long)z * 512);
}

// fused QKV projection: blocks [0,2048) -> qkT GEMM, [2048,3072) -> v2 GEMM
__global__ void __launch_bounds__(256, 2)
hgemm_qkv(const float* __restrict__ b_qkv) {
    extern __shared__ char smem[];
    int bx = blockIdx.x;
    if (bx < 2048) {
        // qkT[feat][bt]: m = feat (32 tiles), n = bt (64 tiles)
        gemm_body(smem, g_wqkT, g_h, g_qkT, NC,
                  512, 512, BT, 0,
                  (bx & 31) * 128, (bx >> 5) * 128,
                  1.0f, b_qkv, nullptr, nullptr, 1, 1, nullptr, 0);
    } else {
        int j = bx - 2048;
        // v2[bt][f]: m = bt (64 tiles), n = f (16 tiles)
        gemm_body(smem, g_h, g_wqkT + 4096LL * 512, g_v2, NC,
                  512, 512, NF, 0,
                  (j >> 4) * 128, (j & 15) * 128,
                  1.0f, nullptr, b_qkv, nullptr, 1, 2, nullptr, 0);
    }
}

extern "C" void kernel_launch(void* const* d_in, const int* in_sizes, int n_in,
                              void* d_out, int out_size) {
    const float* x        = (const float*)d_in[0];
    const float* gn_scale = (const float*)d_in[1];
    const float* gn_bias  = (const float*)d_in[2];
    const float* w_qkv    = (const float*)d_in[3];
    const float* b_qkv    = (const float*)d_in[4];
    const float* w_out    = (const float*)d_in[5];
    const float* b_out    = (const float*)d_in[6];
    float* out = (float*)d_out;

    __half *qkT, *v2, *attnh, *av2, *woutT;
    float* Z;
    cudaGetSymbolAddress((void**)&qkT,   g_qkT);
    cudaGetSymbolAddress((void**)&v2,    g_v2);
    cudaGetSymbolAddress((void**)&attnh, g_attnh);
    cudaGetSymbolAddress((void**)&av2,   g_av2);
    cudaGetSymbolAddress((void**)&woutT, g_woutT);
    cudaGetSymbolAddress((void**)&Z,     g_Z);

    cudaFuncSetAttribute(hgemm,     cudaFuncAttributeMaxDynamicSharedMemorySize, GSMEM);
    cudaFuncSetAttribute(hgemm_qkv, cudaFuncAttributeMaxDynamicSharedMemorySize, GSMEM);

    // 0: fused groupnorm
    gn_fused<<<NB * 32, 256>>>(x, gn_scale, gn_bias);
    // 1: merged weight transposes
    tr_all<<<192 + 1024, 256>>>(w_qkv, w_out);

    // 2: fused QKV projection (qkT + v2 in one launch)
    hgemm_qkv<<<3072, 256, GSMEM>>>(b_qkv);

    // 3: QK logits: [z][c][d] = (1/32) Q·K, fp16 out
    hgemm<<<dim3(NC / 128, NC / 128, 32), 256, GSMEM>>>(
        qkT, qkT + 2048LL * BT, attnh, NT,
        BT, BT, NC,
        NH,
        512 * BT, NT, 512 * BT, NT,
        NC * NC, 4 * NC * NC,
        1.0f / 32.0f, nullptr, nullptr, nullptr, 1, 0, nullptr);

    // 4: E = exp(logit - 2), Z = 1/rowsum (fp16 in place)
    softexp512<<<32 * NC, 256>>>(attnh, Z);

    // 5: AV: av2[b*1024+t][h*512+c] = (1/Z_c)·sum_d V[t,d]·E[c,d]  (m=t, n=c)
    hgemm<<<dim3(NC / 128, NT / 128, 32), 256, GSMEM>>>(
        v2, attnh, av2, NC,
        NF, NC, NF,
        NH,
        512, NT * NF,
        NC * NC, 4 * NC * NC,
        512, NT * NF,
        1.0f, nullptr, nullptr, nullptr, 1, 0, Z);

    // 6: Out: out[b][t][c] = av2 @ woutT^T + b_out + x  (fp32 + resid)
    hgemm<<<dim3(NC / 128, NT / 128, NB), 256, GSMEM>>>(
        av2, woutT, out, NF,
        NF, NF, NC,
        1,
        0, NT * NF, 0, 0,
        0, NT * NC,
        1.0f, nullptr, b_out, x, 0, 0, nullptr);
}

// round 13
// speedup vs baseline: 1.3504x; 1.0653x over previous
#include <cuda_runtime.h>
#include <cuda_fp16.h>
#include <cstdint>

#define NB 8
#define NT 1024
#define NC 512
#define NH 4
#define BT (NB*NT)          // 8192
#define NF 2048             // NH*NC

// ---------------- scratch (device globals) ----------------
__device__ __half g_h[BT * NC];                     // [bt][c]
__device__ __half g_qkT[(long long)4096 * BT];      // rows 0..2047 Q(h*512+c), 2048..4095 K ; [row][bt]
__device__ __half g_v2[(long long)BT * NF];         // [bt][h*512+d]
__device__ __half g_attnh[32 * NC * NC];            // [z][c][d]: E = exp(logit-2), fp16
__device__ float  g_Z[32 * NC];                     // row sums of E (atomic-accumulated)
__device__ __half g_av2[(long long)BT * NF];        // [bt][h*512+c]
__device__ __half g_wqkT[6144 * NC];                // [row][c] row: sec*2048 + h*512 + c (sec 2 = V)
__device__ __half g_woutT[NC * NF];                 // [c][f]

__device__ __forceinline__ uint32_t smem_u32(const void* p) {
    uint32_t a;
    asm("{ .reg .u64 t; cvta.to.shared.u64 t, %1; cvt.u32.u64 %0, t; }" : "=r"(a) : "l"(p));
    return a;
}
#define SWZ(o) ((o) ^ (((o) >> 3) & 0x70))

#define CPASYNC16(dst, src) \
    asm volatile("cp.async.cg.shared.global [%0], [%1], 16;" :: "r"(dst), "l"(src))
#define CP_COMMIT() asm volatile("cp.async.commit_group;" ::: "memory")
#define CP_WAIT1()  asm volatile("cp.async.wait_group 1;" ::: "memory")

#define LDSM4(r0, r1, r2, r3, addr) \
    asm volatile("ldmatrix.sync.aligned.m8n8.x4.shared.b16 {%0,%1,%2,%3}, [%4];" \
        : "=r"(r0), "=r"(r1), "=r"(r2), "=r"(r3) : "r"(addr))

#define HMMA16(d, a0, a1, a2, a3, b0, b1) \
    asm volatile("mma.sync.aligned.m16n8k16.row.col.f32.f16.f16.f32 " \
        "{%0,%1,%2,%3}, {%4,%5,%6,%7}, {%8,%9}, {%0,%1,%2,%3};" \
        : "+f"((d)[0]), "+f"((d)[1]), "+f"((d)[2]), "+f"((d)[3]) \
        : "r"(a0), "r"(a1), "r"(a2), "r"(a3), "r"(b0), "r"(b1))

// ---------------- merged prep: groupnorm + both weight transposes + Z zero ----
// blocks [0,256): groupnorm (b,group); [256,448): w_qkv tr; [448,1472): w_out tr
__global__ void gn_tr(const float* __restrict__ x,
                      const float* __restrict__ scale,
                      const float* __restrict__ bias,
                      const float* __restrict__ wqkv,
                      const float* __restrict__ wout) {
    int blk = blockIdx.x;
    int tid = threadIdx.x;
    if (blk < 256) {
        int b = blk >> 5, g = blk & 31;
        // zero Z (first 64 blocks cover 64*256 = 16384 entries)
        if (blk < 64) g_Z[blk * 256 + tid] = 0.f;
        const float* base = x + (size_t)b * (NT * NC) + g * 16;
        __half* hbase = g_h + (size_t)b * (NT * NC) + g * 16;
        int col = tid & 15;
        float sc = scale[g * 16 + col];
        float bi = bias[g * 16 + col];
        float s = 0.f, ss = 0.f;
        for (int idx = tid; idx < NT * 16; idx += 256) {
            float v = base[(idx >> 4) * NC + (idx & 15)];
            s += v; ss += v * v;
        }
        for (int o = 16; o; o >>= 1) {
            s  += __shfl_xor_sync(0xffffffffu, s,  o);
            ss += __shfl_xor_sync(0xffffffffu, ss, o);
        }
        __shared__ float sa[8], sb[8];
        __shared__ float s_mean, s_rstd;
        int wid = tid >> 5;
        if ((tid & 31) == 0) { sa[wid] = s; sb[wid] = ss; }
        __syncthreads();
        if (tid == 0) {
            float S = 0.f, SS = 0.f;
            #pragma unroll
            for (int i = 0; i < 8; i++) { S += sa[i]; SS += sb[i]; }
            float inv = 1.0f / (NT * 16);
            float mean = S * inv;
            float var  = SS * inv - mean * mean;
            s_mean = mean;
            s_rstd = rsqrtf(var + 1e-5f);
        }
        __syncthreads();
        float mean = s_mean, rstd = s_rstd;
        for (int idx = tid; idx < NT * 16; idx += 256) {
            int off = (idx >> 4) * NC + (idx & 15);
            hbase[off] = __float2half((base[off] - mean) * rstd * sc + bi);
        }
        return;
    }
    __shared__ float t[32][33];
    int tx = tid & 31, ty = tid >> 5;
    if (blk < 448) {
        int q = blk - 256;                 // 0..191
        int sec = q >> 6;
        int within = q & 63;
        int h = within >> 4, ct = within & 15;
        int c0 = ct * 32;
        int fbase = h * 1536 + sec;
        int r0 = sec * 2048 + h * 512 + c0;
        for (int k0 = 0; k0 < 512; k0 += 32) {
            #pragma unroll
            for (int j = 0; j < 4; j++) {
                int k = ty + j * 8;
                t[k][tx] = wqkv[(long long)(k0 + k) * 6144 + fbase + 3 * (c0 + tx)];
            }
            __syncthreads();
            #pragma unroll
            for (int j = 0; j < 4; j++) {
                int cc = ty + j * 8;
                g_wqkT[(long long)(r0 + cc) * 512 + k0 + tx] = __float2half(t[tx][cc]);
            }
            __syncthreads();
        }
    } else {
        int q = blk - 448;                 // 0..1023
        int f0 = (q & 63) * 32, c0 = (q >> 6) * 32;
        #pragma unroll
        for (int j = 0; j < 4; j++)
            t[ty + j * 8][tx] = wout[(long long)(f0 + ty + j * 8) * 512 + c0 + tx];
        __syncthreads();
        #pragma unroll
        for (int j = 0; j < 4; j++)
            g_woutT[(long long)(c0 + ty + j * 8) * 2048 + f0 + tx] = __float2half(t[tx][ty + j * 8]);
    }
}

// ---------------- fp16 mma.sync GEMM body: CTA 128x128, warp 64x32, BK=64 ------
#define STAGEB 32768
#define NSTAGE 3
#define GSMEM (NSTAGE * STAGEB)

__device__ __forceinline__ int qkv_map_m(int r) {
    int sec = r >> 11, rem = r & 2047;
    return (rem >> 9) * 1536 + 3 * (rem & 511) + sec;
}
__device__ __forceinline__ int qkv_map_v(int n) {
    return (n >> 9) * 1536 + 3 * (n & 511) + 2;
}

// emode 0: normal epilogue. emode 1: store exp(v-2) fp16 + atomic row sums into zsum.
// rowscale (AV): divide by zsum row value.
__device__ __forceinline__ void gemm_body(
        char* smem,
        const __half* __restrict__ A, const __half* __restrict__ B, void* __restrict__ Cv,
        int K, int Asm, int Bsn, int Csm, long long cbase, int m0, int n0,
        float alpha,
        const float* __restrict__ bias_m, const float* __restrict__ bias_n,
        const float* __restrict__ resid, int c16, int bmode,
        const float* __restrict__ rowscale, long long rsbase,
        float* __restrict__ zsum, long long zbase, int emode) {
    uint32_t sbase = smem_u32(smem);
    int tid = threadIdx.x, lane = tid & 31, wid = tid >> 5;
    int g = lane >> 2, qid = lane & 3;
    int wm = (wid & 1) * 64, wn = (wid >> 1) * 32;

    A += (long long)m0 * Asm;
    B += (long long)n0 * Bsn;

    int row0 = tid >> 3, q0 = tid & 7;
    const __half* srcA = A + (long long)row0 * Asm + q0 * 8;
    const __half* srcB = B + (long long)row0 * Bsn + q0 * 8;
    uint32_t dstA = sbase + SWZ((uint32_t)(row0 * 128 + q0 * 16));

    float acc[4][4][4];
    #pragma unroll
    for (int i = 0; i < 4; i++)
        #pragma unroll
        for (int j = 0; j < 4; j++)
            #pragma unroll
            for (int qq = 0; qq < 4; qq++) acc[i][j][qq] = 0.f;

    int KB = K >> 6;

    #pragma unroll
    for (int s = 0; s < 2; s++) {
        uint32_t so = s * STAGEB;
        #pragma unroll
        for (int t = 0; t < 4; t++) {
            CPASYNC16(dstA + so + t * 4096,         srcA + s * 64 + (long long)(32 * t) * Asm);
            CPASYNC16(dstA + so + 16384 + t * 4096, srcB + s * 64 + (long long)(32 * t) * Bsn);
        }
        CP_COMMIT();
    }

    uint32_t baseA = (uint32_t)((wm + (lane & 15)) * 128 + (lane >> 4) * 16);
    uint32_t baseB = (uint32_t)((wn + (lane & 7) + ((lane >> 4) & 1) * 8) * 128 + ((lane >> 3) & 1) * 16);

    int st = 0;
    for (int kb = 0; kb < KB; kb++) {
        CP_WAIT1();
        __syncthreads();
        if (kb + 2 < KB) {
            int s2 = st + 2; if (s2 >= NSTAGE) s2 -= NSTAGE;
            uint32_t so = (uint32_t)s2 * STAGEB;
            #pragma unroll
            for (int t = 0; t < 4; t++) {
                CPASYNC16(dstA + so + t * 4096,         srcA + (kb + 2) * 64 + (long long)(32 * t) * Asm);
                CPASYNC16(dstA + so + 16384 + t * 4096, srcB + (kb + 2) * 64 + (long long)(32 * t) * Bsn);
            }
        }
        CP_COMMIT();

        uint32_t sA = sbase + st * STAGEB;
        uint32_t sB = sA + 16384;

        #pragma unroll
        for (int ks = 0; ks < 4; ks++) {
            uint32_t a[4][4], bf[2][4];
            #pragma unroll
            for (int mt = 0; mt < 4; mt++)
                LDSM4(a[mt][0], a[mt][1], a[mt][2], a[mt][3],
                      sA + SWZ(baseA + mt * 2048 + ks * 32));
            #pragma unroll
            for (int ntp = 0; ntp < 2; ntp++)
                LDSM4(bf[ntp][0], bf[ntp][1], bf[ntp][2], bf[ntp][3],
                      sB + SWZ(baseB + ntp * 2048 + ks * 32));
            #pragma unroll
            for (int mt = 0; mt < 4; mt++)
                #pragma unroll
                for (int nt = 0; nt < 4; nt++) {
                    uint32_t b0 = bf[nt >> 1][(nt & 1) * 2];
                    uint32_t b1 = bf[nt >> 1][(nt & 1) * 2 + 1];
                    HMMA16(acc[mt][nt], a[mt][0], a[mt][1], a[mt][2], a[mt][3], b0, b1);
                }
        }
        st++; if (st == NSTAGE) st = 0;
    }

    // ---------------- epilogue ----------------
    #pragma unroll
    for (int mt = 0; mt < 4; mt++) {
        int r = m0 + wm + 16 * mt + g;
        float bm0 = 0.f, bm1 = 0.f;
        if (bias_m) {
            if (bmode == 1) { bm0 = bias_m[qkv_map_m(r)]; bm1 = bias_m[qkv_map_m(r + 8)]; }
            else            { bm0 = bias_m[r]; bm1 = bias_m[r + 8]; }
        }
        float zs0 = 0.f, zs1 = 0.f;
        #pragma unroll
        for (int nt = 0; nt < 4; nt++) {
            float* c = acc[mt][nt];
            int n = n0 + wn + 8 * nt + qid * 2;
            long long o0 = cbase + (long long)r * Csm + n;
            long long o1 = cbase + (long long)(r + 8) * Csm + n;
            if (emode) {
                float e00 = __expf(c[0] * alpha - 2.0f);
                float e01 = __expf(c[1] * alpha - 2.0f);
                float e10 = __expf(c[2] * alpha - 2.0f);
                float e11 = __expf(c[3] * alpha - 2.0f);
                zs0 += e00 + e01; zs1 += e10 + e11;
                *(__half2*)((__half*)Cv + o0) = __floats2half2_rn(e00, e01);
                *(__half2*)((__half*)Cv + o1) = __floats2half2_rn(e10, e11);
                continue;
            }
            float bn0 = 0.f, bn1 = 0.f;
            if (bias_n) {
                if (bmode == 2) { bn0 = bias_n[qkv_map_v(n)]; bn1 = bias_n[qkv_map_v(n + 1)]; }
                else            { bn0 = bias_n[n]; bn1 = bias_n[n + 1]; }
            }
            float v00 = c[0] * alpha + bm0 + bn0;
            float v01 = c[1] * alpha + bm0 + bn1;
            float v10 = c[2] * alpha + bm1 + bn0;
            float v11 = c[3] * alpha + bm1 + bn1;
            if (rowscale) {
                float rs0 = 1.0f / rowscale[rsbase + n];
                float rs1 = 1.0f / rowscale[rsbase + n + 1];
                v00 *= rs0; v01 *= rs1; v10 *= rs0; v11 *= rs1;
            }
            if (c16) {
                *(__half2*)((__half*)Cv + o0) = __floats2half2_rn(v00, v01);
                *(__half2*)((__half*)Cv + o1) = __floats2half2_rn(v10, v11);
            } else {
                float* C = (float*)Cv;
                if (resid) {
                    v00 += resid[o0]; v01 += resid[o0 + 1];
                    v10 += resid[o1]; v11 += resid[o1 + 1];
                }
                *(float2*)(C + o0) = make_float2(v00, v01);
                *(float2*)(C + o1) = make_float2(v10, v11);
            }
        }
        if (emode) {
            // reduce across the 4 qid lanes (cols), then one atomic per row per warp
            zs0 += __shfl_xor_sync(0xffffffffu, zs0, 1);
            zs0 += __shfl_xor_sync(0xffffffffu, zs0, 2);
            zs1 += __shfl_xor_sync(0xffffffffu, zs1, 1);
            zs1 += __shfl_xor_sync(0xffffffffu, zs1, 2);
            if (qid == 0) {
                atomicAdd(&zsum[zbase + r], zs0);
                atomicAdd(&zsum[zbase + r + 8], zs1);
            }
        }
    }
}

// generic batched wrapper
__global__ void __launch_bounds__(256, 2)
hgemm(const __half* __restrict__ A, const __half* __restrict__ B, void* __restrict__ Cv,
      int K, int Asm, int Bsn, int Csm,
      int zInner, int Abi, int Abo, int Bbi, int Bbo,
      int Cbi, int Cbo, float alpha,
      const float* __restrict__ bias_m, const float* __restrict__ bias_n,
      const float* __restrict__ resid, int c16, int bmode,
      const float* __restrict__ rowscale, float* __restrict__ zsum, int emode) {
    extern __shared__ char smem[];
    int z = blockIdx.z;
    int zi = z % zInner, zo = z / zInner;
    gemm_body(smem,
              A + (long long)zi * Abi + (long long)zo * Abo,
              B + (long long)zi * Bbi + (long long)zo * Bbo,
              Cv, K, Asm, Bsn, Csm,
              (long long)zi * Cbi + (long long)zo * Cbo,
              blockIdx.y * 128, blockIdx.x * 128,
              alpha, bias_m, bias_n, resid, c16, bmode,
              rowscale, (long long)z * 512,
              zsum, (long long)z * 512, emode);
}

// fused QKV projection: blocks [0,2048) -> qkT GEMM, [2048,3072) -> v2 GEMM
__global__ void __launch_bounds__(256, 2)
hgemm_qkv(const float* __restrict__ b_qkv) {
    extern __shared__ char smem[];
    int bx = blockIdx.x;
    if (bx < 2048) {
        gemm_body(smem, g_wqkT, g_h, g_qkT, NC,
                  512, 512, BT, 0,
                  (bx & 31) * 128, (bx >> 5) * 128,
                  1.0f, b_qkv, nullptr, nullptr, 1, 1, nullptr, 0, nullptr, 0, 0);
    } else {
        int j = bx - 2048;
        gemm_body(smem, g_h, g_wqkT + 4096LL * 512, g_v2, NC,
                  512, 512, NF, 0,
                  (j >> 4) * 128, (j & 15) * 128,
                  1.0f, nullptr, b_qkv, nullptr, 1, 2, nullptr, 0, nullptr, 0, 0);
    }
}

extern "C" void kernel_launch(void* const* d_in, const int* in_sizes, int n_in,
                              void* d_out, int out_size) {
    const float* x        = (const float*)d_in[0];
    const float* gn_scale = (const float*)d_in[1];
    const float* gn_bias  = (const float*)d_in[2];
    const float* w_qkv    = (const float*)d_in[3];
    const float* b_qkv    = (const float*)d_in[4];
    const float* w_out    = (const float*)d_in[5];
    const float* b_out    = (const float*)d_in[6];
    float* out = (float*)d_out;

    __half *qkT, *v2, *attnh, *av2, *woutT;
    float* Z;
    cudaGetSymbolAddress((void**)&qkT,   g_qkT);
    cudaGetSymbolAddress((void**)&v2,    g_v2);
    cudaGetSymbolAddress((void**)&attnh, g_attnh);
    cudaGetSymbolAddress((void**)&av2,   g_av2);
    cudaGetSymbolAddress((void**)&woutT, g_woutT);
    cudaGetSymbolAddress((void**)&Z,     g_Z);

    cudaFuncSetAttribute(hgemm,     cudaFuncAttributeMaxDynamicSharedMemorySize, GSMEM);
    cudaFuncSetAttribute(hgemm_qkv, cudaFuncAttributeMaxDynamicSharedMemorySize, GSMEM);

    // 0: merged prep (groupnorm + transposes + Z zero)
    gn_tr<<<1472, 256>>>(x, gn_scale, gn_bias, w_qkv, w_out);

    // 1: fused QKV projection (qkT + v2 in one launch)
    hgemm_qkv<<<3072, 256, GSMEM>>>(b_qkv);

    // 2: QK logits -> E = exp(l-2) fp16 + row-sum atomics into Z
    hgemm<<<dim3(NC / 128, NC / 128, 32), 256, GSMEM>>>(
        qkT, qkT + 2048LL * BT, attnh, NT,
        BT, BT, NC,
        NH,
        512 * BT, NT, 512 * BT, NT,
        NC * NC, 4 * NC * NC,
        1.0f / 32.0f, nullptr, nullptr, nullptr, 1, 0, nullptr, Z, 1);

    // 3: AV: av2[b*1024+t][h*512+c] = (1/Z_c)·sum_d V[t,d]·E[c,d]  (m=t, n=c)
    hgemm<<<dim3(NC / 128, NT / 128, 32), 256, GSMEM>>>(
        v2, attnh, av2, NC,
        NF, NC, NF,
        NH,
        512, NT * NF,
        NC * NC, 4 * NC * NC,
        512, NT * NF,
        1.0f, nullptr, nullptr, nullptr, 1, 0, Z, nullptr, 0);

    // 4: Out: out[b][t][c] = av2 @ woutT^T + b_out + x  (fp32 + resid)
    hgemm<<<dim3(NC / 128, NT / 128, NB), 256, GSMEM>>>(
        av2, woutT, out, NF,
        NF, NF, NC,
        1,
        0, NT * NF, 0, 0,
        0, NT * NC,
        1.0f, nullptr, b_out, x, 0, 0, nullptr, nullptr, 0);
}

// round 14
// speedup vs baseline: 1.3749x; 1.0182x over previous
#include <cuda_runtime.h>
#include <cuda_fp16.h>
#include <cstdint>

#define NB 8
#define NT 1024
#define NC 512
#define NH 4
#define BT (NB*NT)          // 8192
#define NF 2048             // NH*NC

// ---------------- scratch (device globals) ----------------
__device__ __half g_h[BT * NC];                     // [bt][c]
__device__ __half g_qkT[(long long)4096 * BT];      // rows 0..2047 Q(h*512+c), 2048..4095 K ; [row][bt]
__device__ __half g_v2[(long long)BT * NF];         // [bt][h*512+d]
__device__ __half g_attnh[32 * NC * NC];            // [z][c][d]: E = exp(logit-2), fp16
__device__ float  g_Z[32 * NC];                     // row sums of E (atomic-accumulated)
__device__ __half g_av2[(long long)BT * NF];        // [bt][h*512+c]
__device__ __half g_wqkT[6144 * NC];                // [row][c] row: sec*2048 + h*512 + c (sec 2 = V)
__device__ __half g_woutT[NC * NF];                 // [c][f]

__device__ __forceinline__ uint32_t smem_u32(const void* p) {
    uint32_t a;
    asm("{ .reg .u64 t; cvta.to.shared.u64 t, %1; cvt.u32.u64 %0, t; }" : "=r"(a) : "l"(p));
    return a;
}
#define SWZ(o) ((o) ^ (((o) >> 3) & 0x70))

#define CPASYNC16(dst, src) \
    asm volatile("cp.async.cg.shared.global [%0], [%1], 16;" :: "r"(dst), "l"(src))
#define CP_COMMIT() asm volatile("cp.async.commit_group;" ::: "memory")
#define CP_WAIT1()  asm volatile("cp.async.wait_group 1;" ::: "memory")

#define LDSM4(r0, r1, r2, r3, addr) \
    asm volatile("ldmatrix.sync.aligned.m8n8.x4.shared.b16 {%0,%1,%2,%3}, [%4];" \
        : "=r"(r0), "=r"(r1), "=r"(r2), "=r"(r3) : "r"(addr))

#define HMMA16(d, a0, a1, a2, a3, b0, b1) \
    asm volatile("mma.sync.aligned.m16n8k16.row.col.f32.f16.f16.f32 " \
        "{%0,%1,%2,%3}, {%4,%5,%6,%7}, {%8,%9}, {%0,%1,%2,%3};" \
        : "+f"((d)[0]), "+f"((d)[1]), "+f"((d)[2]), "+f"((d)[3]) \
        : "r"(a0), "r"(a1), "r"(a2), "r"(a3), "r"(b0), "r"(b1))

// ---------------- merged prep: groupnorm + both weight transposes + Z zero ----
__global__ void gn_tr(const float* __restrict__ x,
                      const float* __restrict__ scale,
                      const float* __restrict__ bias,
                      const float* __restrict__ wqkv,
                      const float* __restrict__ wout) {
    int blk = blockIdx.x;
    int tid = threadIdx.x;
    if (blk < 256) {
        int b = blk >> 5, g = blk & 31;
        if (blk < 64) g_Z[blk * 256 + tid] = 0.f;
        const float* base = x + (size_t)b * (NT * NC) + g * 16;
        __half* hbase = g_h + (size_t)b * (NT * NC) + g * 16;
        int col = tid & 15;
        float sc = scale[g * 16 + col];
        float bi = bias[g * 16 + col];
        float s = 0.f, ss = 0.f;
        for (int idx = tid; idx < NT * 16; idx += 256) {
            float v = base[(idx >> 4) * NC + (idx & 15)];
            s += v; ss += v * v;
        }
        for (int o = 16; o; o >>= 1) {
            s  += __shfl_xor_sync(0xffffffffu, s,  o);
            ss += __shfl_xor_sync(0xffffffffu, ss, o);
        }
        __shared__ float sa[8], sb[8];
        __shared__ float s_mean, s_rstd;
        int wid = tid >> 5;
        if ((tid & 31) == 0) { sa[wid] = s; sb[wid] = ss; }
        __syncthreads();
        if (tid == 0) {
            float S = 0.f, SS = 0.f;
            #pragma unroll
            for (int i = 0; i < 8; i++) { S += sa[i]; SS += sb[i]; }
            float inv = 1.0f / (NT * 16);
            float mean = S * inv;
            float var  = SS * inv - mean * mean;
            s_mean = mean;
            s_rstd = rsqrtf(var + 1e-5f);
        }
        __syncthreads();
        float mean = s_mean, rstd = s_rstd;
        for (int idx = tid; idx < NT * 16; idx += 256) {
            int off = (idx >> 4) * NC + (idx & 15);
            hbase[off] = __float2half((base[off] - mean) * rstd * sc + bi);
        }
        return;
    }
    __shared__ float t[32][33];
    int tx = tid & 31, ty = tid >> 5;
    if (blk < 448) {
        int q = blk - 256;
        int sec = q >> 6;
        int within = q & 63;
        int h = within >> 4, ct = within & 15;
        int c0 = ct * 32;
        int fbase = h * 1536 + sec;
        int r0 = sec * 2048 + h * 512 + c0;
        for (int k0 = 0; k0 < 512; k0 += 32) {
            #pragma unroll
            for (int j = 0; j < 4; j++) {
                int k = ty + j * 8;
                t[k][tx] = wqkv[(long long)(k0 + k) * 6144 + fbase + 3 * (c0 + tx)];
            }
            __syncthreads();
            #pragma unroll
            for (int j = 0; j < 4; j++) {
                int cc = ty + j * 8;
                g_wqkT[(long long)(r0 + cc) * 512 + k0 + tx] = __float2half(t[tx][cc]);
            }
            __syncthreads();
        }
    } else {
        int q = blk - 448;
        int f0 = (q & 63) * 32, c0 = (q >> 6) * 32;
        #pragma unroll
        for (int j = 0; j < 4; j++)
            t[ty + j * 8][tx] = wout[(long long)(f0 + ty + j * 8) * 512 + c0 + tx];
        __syncthreads();
        #pragma unroll
        for (int j = 0; j < 4; j++)
            g_woutT[(long long)(c0 + ty + j * 8) * 2048 + f0 + tx] = __float2half(t[tx][ty + j * 8]);
    }
}

// ---------------- fp16 mma.sync GEMM body: CTA 128x128, warp 64x32, BK=64 ------
#define STAGEB 32768
#define NSTAGE 3
#define GSMEM (NSTAGE * STAGEB)

__device__ __forceinline__ int qkv_map_m(int r) {
    int sec = r >> 11, rem = r & 2047;
    return (rem >> 9) * 1536 + 3 * (rem & 511) + sec;
}
__device__ __forceinline__ int qkv_map_v(int n) {
    return (n >> 9) * 1536 + 3 * (n & 511) + 2;
}

__device__ __forceinline__ void gemm_body(
        char* smem,
        const __half* __restrict__ A, const __half* __restrict__ B, void* __restrict__ Cv,
        int K, int Asm, int Bsn, int Csm, long long cbase, int m0, int n0,
        float alpha,
        const float* __restrict__ bias_m, const float* __restrict__ bias_n,
        const float* __restrict__ resid, int c16, int bmode,
        const float* __restrict__ rowscale, long long rsbase,
        float* __restrict__ zsum, long long zbase, int emode) {
    uint32_t sbase = smem_u32(smem);
    int tid = threadIdx.x, lane = tid & 31, wid = tid >> 5;
    int g = lane >> 2, qid = lane & 3;
    int wm = (wid & 1) * 64, wn = (wid >> 1) * 32;

    A += (long long)m0 * Asm;
    B += (long long)n0 * Bsn;

    int row0 = tid >> 3, q0 = tid & 7;
    const __half* srcA = A + (long long)row0 * Asm + q0 * 8;
    const __half* srcB = B + (long long)row0 * Bsn + q0 * 8;
    uint32_t dstA = sbase + SWZ((uint32_t)(row0 * 128 + q0 * 16));

    float acc[4][4][4];
    #pragma unroll
    for (int i = 0; i < 4; i++)
        #pragma unroll
        for (int j = 0; j < 4; j++)
            #pragma unroll
            for (int qq = 0; qq < 4; qq++) acc[i][j][qq] = 0.f;

    int KB = K >> 6;

    #pragma unroll
    for (int s = 0; s < 2; s++) {
        uint32_t so = s * STAGEB;
        #pragma unroll
        for (int t = 0; t < 4; t++) {
            CPASYNC16(dstA + so + t * 4096,         srcA + s * 64 + (long long)(32 * t) * Asm);
            CPASYNC16(dstA + so + 16384 + t * 4096, srcB + s * 64 + (long long)(32 * t) * Bsn);
        }
        CP_COMMIT();
    }

    uint32_t baseA = (uint32_t)((wm + (lane & 15)) * 128 + (lane >> 4) * 16);
    uint32_t baseB = (uint32_t)((wn + (lane & 7) + ((lane >> 4) & 1) * 8) * 128 + ((lane >> 3) & 1) * 16);

    int st = 0;
    for (int kb = 0; kb < KB; kb++) {
        CP_WAIT1();
        __syncthreads();
        if (kb + 2 < KB) {
            int s2 = st + 2; if (s2 >= NSTAGE) s2 -= NSTAGE;
            uint32_t so = (uint32_t)s2 * STAGEB;
            #pragma unroll
            for (int t = 0; t < 4; t++) {
                CPASYNC16(dstA + so + t * 4096,         srcA + (kb + 2) * 64 + (long long)(32 * t) * Asm);
                CPASYNC16(dstA + so + 16384 + t * 4096, srcB + (kb + 2) * 64 + (long long)(32 * t) * Bsn);
            }
        }
        CP_COMMIT();

        uint32_t sA = sbase + st * STAGEB;
        uint32_t sB = sA + 16384;

        #pragma unroll
        for (int ks = 0; ks < 4; ks++) {
            uint32_t a[4][4], bf[2][4];
            #pragma unroll
            for (int mt = 0; mt < 4; mt++)
                LDSM4(a[mt][0], a[mt][1], a[mt][2], a[mt][3],
                      sA + SWZ(baseA + mt * 2048 + ks * 32));
            #pragma unroll
            for (int ntp = 0; ntp < 2; ntp++)
                LDSM4(bf[ntp][0], bf[ntp][1], bf[ntp][2], bf[ntp][3],
                      sB + SWZ(baseB + ntp * 2048 + ks * 32));
            #pragma unroll
            for (int mt = 0; mt < 4; mt++)
                #pragma unroll
                for (int nt = 0; nt < 4; nt++) {
                    uint32_t b0 = bf[nt >> 1][(nt & 1) * 2];
                    uint32_t b1 = bf[nt >> 1][(nt & 1) * 2 + 1];
                    HMMA16(acc[mt][nt], a[mt][0], a[mt][1], a[mt][2], a[mt][3], b0, b1);
                }
        }
        st++; if (st == NSTAGE) st = 0;
    }

    // ---------------- epilogue ----------------
    #pragma unroll
    for (int mt = 0; mt < 4; mt++) {
        int r = m0 + wm + 16 * mt + g;
        float bm0 = 0.f, bm1 = 0.f;
        if (bias_m) {
            if (bmode == 1) { bm0 = bias_m[qkv_map_m(r)]; bm1 = bias_m[qkv_map_m(r + 8)]; }
            else            { bm0 = bias_m[r]; bm1 = bias_m[r + 8]; }
        }
        float zs0 = 0.f, zs1 = 0.f;
        #pragma unroll
        for (int nt = 0; nt < 4; nt++) {
            float* c = acc[mt][nt];
            int n = n0 + wn + 8 * nt + qid * 2;
            long long o0 = cbase + (long long)r * Csm + n;
            long long o1 = cbase + (long long)(r + 8) * Csm + n;
            if (emode) {
                float e00 = __expf(c[0] * alpha - 2.0f);
                float e01 = __expf(c[1] * alpha - 2.0f);
                float e10 = __expf(c[2] * alpha - 2.0f);
                float e11 = __expf(c[3] * alpha - 2.0f);
                zs0 += e00 + e01; zs1 += e10 + e11;
                *(__half2*)((__half*)Cv + o0) = __floats2half2_rn(e00, e01);
                *(__half2*)((__half*)Cv + o1) = __floats2half2_rn(e10, e11);
                continue;
            }
            float bn0 = 0.f, bn1 = 0.f;
            if (bias_n) {
                if (bmode == 2) { bn0 = bias_n[qkv_map_v(n)]; bn1 = bias_n[qkv_map_v(n + 1)]; }
                else            { bn0 = bias_n[n]; bn1 = bias_n[n + 1]; }
            }
            float v00 = c[0] * alpha + bm0 + bn0;
            float v01 = c[1] * alpha + bm0 + bn1;
            float v10 = c[2] * alpha + bm1 + bn0;
            float v11 = c[3] * alpha + bm1 + bn1;
            if (rowscale) {
                float rs0 = 1.0f / rowscale[rsbase + n];
                float rs1 = 1.0f / rowscale[rsbase + n + 1];
                v00 *= rs0; v01 *= rs1; v10 *= rs0; v11 *= rs1;
            }
            if (c16) {
                *(__half2*)((__half*)Cv + o0) = __floats2half2_rn(v00, v01);
                *(__half2*)((__half*)Cv + o1) = __floats2half2_rn(v10, v11);
            } else {
                float* C = (float*)Cv;
                if (resid) {
                    v00 += resid[o0]; v01 += resid[o0 + 1];
                    v10 += resid[o1]; v11 += resid[o1 + 1];
                }
                *(float2*)(C + o0) = make_float2(v00, v01);
                *(float2*)(C + o1) = make_float2(v10, v11);
            }
        }
        if (emode) {
            zs0 += __shfl_xor_sync(0xffffffffu, zs0, 1);
            zs0 += __shfl_xor_sync(0xffffffffu, zs0, 2);
            zs1 += __shfl_xor_sync(0xffffffffu, zs1, 1);
            zs1 += __shfl_xor_sync(0xffffffffu, zs1, 2);
            if (qid == 0) {
                atomicAdd(&zsum[zbase + r], zs0);
                atomicAdd(&zsum[zbase + r + 8], zs1);
            }
        }
    }
}

// generic batched wrapper (used for AV + Out)
__global__ void __launch_bounds__(256, 2)
hgemm(const __half* __restrict__ A, const __half* __restrict__ B, void* __restrict__ Cv,
      int K, int Asm, int Bsn, int Csm,
      int zInner, int Abi, int Abo, int Bbi, int Bbo,
      int Cbi, int Cbo, float alpha,
      const float* __restrict__ bias_m, const float* __restrict__ bias_n,
      const float* __restrict__ resid, int c16, int bmode,
      const float* __restrict__ rowscale, float* __restrict__ zsum, int emode) {
    extern __shared__ char smem[];
    int z = blockIdx.z;
    int zi = z % zInner, zo = z / zInner;
    gemm_body(smem,
              A + (long long)zi * Abi + (long long)zo * Abo,
              B + (long long)zi * Bbi + (long long)zo * Bbo,
              Cv, K, Asm, Bsn, Csm,
              (long long)zi * Cbi + (long long)zo * Cbo,
              blockIdx.y * 128, blockIdx.x * 128,
              alpha, bias_m, bias_n, resid, c16, bmode,
              rowscale, (long long)z * 512,
              zsum, (long long)z * 512, emode);
}

// Q,K projection: 2048 blocks -> qkT[feat][bt]
__global__ void __launch_bounds__(256, 2)
hgemm_2a(const float* __restrict__ b_qkv) {
    extern __shared__ char smem[];
    int bx = blockIdx.x;
    gemm_body(smem, g_wqkT, g_h, g_qkT, NC,
              512, 512, BT, 0,
              (bx & 31) * 128, (bx >> 5) * 128,
              1.0f, b_qkv, nullptr, nullptr, 1, 1, nullptr, 0, nullptr, 0, 0);
}

// merged: blocks [0,512) = QK logits->E tiles (16 K-blocks, LPT-first);
//         blocks [512,1536) = V projection tiles (8 K-blocks)
__global__ void __launch_bounds__(256, 2)
hgemm_qk_v(const float* __restrict__ b_qkv) {
    extern __shared__ char smem[];
    int bx = blockIdx.x;
    float* Zp;
    asm("cvta.global.u64 %0, %1;" : "=l"(Zp) : "l"(g_Z));
    if (bx < 512) {
        int z = bx >> 4;                 // b*4+h
        int zi = z & 3, zo = z >> 2;     // h, b
        int m0 = ((bx >> 2) & 3) * 128;
        int n0 = (bx & 3) * 128;
        gemm_body(smem,
                  g_qkT + (long long)zi * 512 * BT + (long long)zo * NT,
                  g_qkT + 2048LL * BT + (long long)zi * 512 * BT + (long long)zo * NT,
                  g_attnh, NT,
                  BT, BT, NC,
                  (long long)z * NC * NC, m0, n0,
                  1.0f / 32.0f, nullptr, nullptr, nullptr, 1, 0,
                  nullptr, 0, Zp, (long long)z * 512, 1);
    } else {
        int j = bx - 512;                // 0..1023
        gemm_body(smem, g_h, g_wqkT + 4096LL * 512, g_v2, NC,
                  512, 512, NF, 0,
                  (j >> 4) * 128, (j & 15) * 128,
                  1.0f, nullptr, b_qkv, nullptr, 1, 2, nullptr, 0, nullptr, 0, 0);
    }
}

extern "C" void kernel_launch(void* const* d_in, const int* in_sizes, int n_in,
                              void* d_out, int out_size) {
    const float* x        = (const float*)d_in[0];
    const float* gn_scale = (const float*)d_in[1];
    const float* gn_bias  = (const float*)d_in[2];
    const float* w_qkv    = (const float*)d_in[3];
    const float* b_qkv    = (const float*)d_in[4];
    const float* w_out    = (const float*)d_in[5];
    const float* b_out    = (const float*)d_in[6];
    float* out = (float*)d_out;

    __half *v2, *attnh, *av2, *woutT;
    float* Z;
    cudaGetSymbolAddress((void**)&v2,    g_v2);
    cudaGetSymbolAddress((void**)&attnh, g_attnh);
    cudaGetSymbolAddress((void**)&av2,   g_av2);
    cudaGetSymbolAddress((void**)&woutT, g_woutT);
    cudaGetSymbolAddress((void**)&Z,     g_Z);

    cudaFuncSetAttribute(hgemm,      cudaFuncAttributeMaxDynamicSharedMemorySize, GSMEM);
    cudaFuncSetAttribute(hgemm_2a,   cudaFuncAttributeMaxDynamicSharedMemorySize, GSMEM);
    cudaFuncSetAttribute(hgemm_qk_v, cudaFuncAttributeMaxDynamicSharedMemorySize, GSMEM);

    // 0: merged prep (groupnorm + transposes + Z zero)
    gn_tr<<<1472, 256>>>(x, gn_scale, gn_bias, w_qkv, w_out);

    // 1: Q,K projection (2048 CTAs = 6.92 waves)
    hgemm_2a<<<2048, 256, GSMEM>>>(b_qkv);

    // 2: QK logits -> E + Z atomics, co-scheduled with V projection
    hgemm_qk_v<<<1536, 256, GSMEM>>>(b_qkv);

    // 3: AV: av2[b*1024+t][h*512+c] = (1/Z_c)·sum_d V[t,d]·E[c,d]
    hgemm<<<dim3(NC / 128, NT / 128, 32), 256, GSMEM>>>(
        v2, attnh, av2, NC,
        NF, NC, NF,
        NH,
        512, NT * NF,
        NC * NC, 4 * NC * NC,
        512, NT * NF,
        1.0f, nullptr, nullptr, nullptr, 1, 0, Z, nullptr, 0);

    // 4: Out: out[b][t][c] = av2 @ woutT^T + b_out + x  (fp32 + resid)
    hgemm<<<dim3(NC / 128, NT / 128, NB), 256, GSMEM>>>(
        av2, woutT, out, NF,
        NF, NF, NC,
        1,
        0, NT * NF, 0, 0,
        0, NT * NC,
        1.0f, nullptr, b_out, x, 0, 0, nullptr, nullptr, 0);
}

// round 15
// speedup vs baseline: 1.4402x; 1.0475x over previous
#include <cuda_runtime.h>
#include <cuda_fp16.h>
#include <cstdint>

#define NB 8
#define NT 1024
#define NC 512
#define NH 4
#define BT (NB*NT)          // 8192
#define NF 2048             // NH*NC

// ---------------- scratch (device globals) ----------------
__device__ __half g_h[BT * NC];                     // [bt][c]
__device__ __half g_qkT[(long long)4096 * BT];      // rows 0..2047 Q(h*512+c), 2048..4095 K ; [row][bt]
__device__ __half g_v2[(long long)BT * NF];         // [bt][h*512+d]
__device__ __half g_attnh[32 * NC * NC];            // [z][c][d]: E = exp(logit-2), fp16
__device__ float  g_Z[32 * NC];                     // row sums of E (atomic-accumulated)
__device__ __half g_av2[(long long)BT * NF];        // [bt][h*512+c]
__device__ __half g_wqkT[6144 * NC];                // [row][c] row: sec*2048 + h*512 + c (sec 2 = V)
__device__ __half g_woutT[NC * NF];                 // [c][f]
__device__ int    g_cnt[64];                        // AV completion counters [b*8 + t-tile]

__device__ __forceinline__ uint32_t smem_u32(const void* p) {
    uint32_t a;
    asm("{ .reg .u64 t; cvta.to.shared.u64 t, %1; cvt.u32.u64 %0, t; }" : "=r"(a) : "l"(p));
    return a;
}
#define SWZ(o) ((o) ^ (((o) >> 3) & 0x70))

#define CPASYNC16(dst, src) \
    asm volatile("cp.async.cg.shared.global [%0], [%1], 16;" :: "r"(dst), "l"(src))
#define CP_COMMIT() asm volatile("cp.async.commit_group;" ::: "memory")
#define CP_WAIT1()  asm volatile("cp.async.wait_group 1;" ::: "memory")

#define LDSM4(r0, r1, r2, r3, addr) \
    asm volatile("ldmatrix.sync.aligned.m8n8.x4.shared.b16 {%0,%1,%2,%3}, [%4];" \
        : "=r"(r0), "=r"(r1), "=r"(r2), "=r"(r3) : "r"(addr))

#define HMMA16(d, a0, a1, a2, a3, b0, b1) \
    asm volatile("mma.sync.aligned.m16n8k16.row.col.f32.f16.f16.f32 " \
        "{%0,%1,%2,%3}, {%4,%5,%6,%7}, {%8,%9}, {%0,%1,%2,%3};" \
        : "+f"((d)[0]), "+f"((d)[1]), "+f"((d)[2]), "+f"((d)[3]) \
        : "r"(a0), "r"(a1), "r"(a2), "r"(a3), "r"(b0), "r"(b1))

// ---------------- merged prep: groupnorm + transposes + counter/Z zero ----------
__global__ void gn_tr(const float* __restrict__ x,
                      const float* __restrict__ scale,
                      const float* __restrict__ bias,
                      const float* __restrict__ wqkv,
                      const float* __restrict__ wout) {
    int blk = blockIdx.x;
    int tid = threadIdx.x;
    if (blk < 256) {
        int b = blk >> 5, g = blk & 31;
        if (blk < 64) g_Z[blk * 256 + tid] = 0.f;
        if (blk == 64 && tid < 64) g_cnt[tid] = 0;
        const float* base = x + (size_t)b * (NT * NC) + g * 16;
        __half* hbase = g_h + (size_t)b * (NT * NC) + g * 16;
        int col = tid & 15;
        float sc = scale[g * 16 + col];
        float bi = bias[g * 16 + col];
        float s = 0.f, ss = 0.f;
        for (int idx = tid; idx < NT * 16; idx += 256) {
            float v = base[(idx >> 4) * NC + (idx & 15)];
            s += v; ss += v * v;
        }
        for (int o = 16; o; o >>= 1) {
            s  += __shfl_xor_sync(0xffffffffu, s,  o);
            ss += __shfl_xor_sync(0xffffffffu, ss, o);
        }
        __shared__ float sa[8], sb[8];
        __shared__ float s_mean, s_rstd;
        int wid = tid >> 5;
        if ((tid & 31) == 0) { sa[wid] = s; sb[wid] = ss; }
        __syncthreads();
        if (tid == 0) {
            float S = 0.f, SS = 0.f;
            #pragma unroll
            for (int i = 0; i < 8; i++) { S += sa[i]; SS += sb[i]; }
            float inv = 1.0f / (NT * 16);
            float mean = S * inv;
            float var  = SS * inv - mean * mean;
            s_mean = mean;
            s_rstd = rsqrtf(var + 1e-5f);
        }
        __syncthreads();
        float mean = s_mean, rstd = s_rstd;
        for (int idx = tid; idx < NT * 16; idx += 256) {
            int off = (idx >> 4) * NC + (idx & 15);
            hbase[off] = __float2half((base[off] - mean) * rstd * sc + bi);
        }
        return;
    }
    __shared__ float t[32][33];
    int tx = tid & 31, ty = tid >> 5;
    if (blk < 448) {
        int q = blk - 256;
        int sec = q >> 6;
        int within = q & 63;
        int h = within >> 4, ct = within & 15;
        int c0 = ct * 32;
        int fbase = h * 1536 + sec;
        int r0 = sec * 2048 + h * 512 + c0;
        for (int k0 = 0; k0 < 512; k0 += 32) {
            #pragma unroll
            for (int j = 0; j < 4; j++) {
                int k = ty + j * 8;
                t[k][tx] = wqkv[(long long)(k0 + k) * 6144 + fbase + 3 * (c0 + tx)];
            }
            __syncthreads();
            #pragma unroll
            for (int j = 0; j < 4; j++) {
                int cc = ty + j * 8;
                g_wqkT[(long long)(r0 + cc) * 512 + k0 + tx] = __float2half(t[tx][cc]);
            }
            __syncthreads();
        }
    } else {
        int q = blk - 448;
        int f0 = (q & 63) * 32, c0 = (q >> 6) * 32;
        #pragma unroll
        for (int j = 0; j < 4; j++)
            t[ty + j * 8][tx] = wout[(long long)(f0 + ty + j * 8) * 512 + c0 + tx];
        __syncthreads();
        #pragma unroll
        for (int j = 0; j < 4; j++)
            g_woutT[(long long)(c0 + ty + j * 8) * 2048 + f0 + tx] = __float2half(t[tx][ty + j * 8]);
    }
}

// ---------------- fp16 mma.sync GEMM body: CTA 128x128, warp 64x32, BK=64 ------
#define STAGEB 32768
#define NSTAGE 3
#define GSMEM (NSTAGE * STAGEB)

__device__ __forceinline__ int qkv_map_m(int r) {
    int sec = r >> 11, rem = r & 2047;
    return (rem >> 9) * 1536 + 3 * (rem & 511) + sec;
}
__device__ __forceinline__ int qkv_map_v(int n) {
    return (n >> 9) * 1536 + 3 * (n & 511) + 2;
}

__device__ __forceinline__ void gemm_body(
        char* smem,
        const __half* __restrict__ A, const __half* __restrict__ B, void* __restrict__ Cv,
        int K, int Asm, int Bsn, int Csm, long long cbase, int m0, int n0,
        float alpha,
        const float* __restrict__ bias_m, const float* __restrict__ bias_n,
        const float* __restrict__ resid, int c16, int bmode,
        const float* __restrict__ rowscale, long long rsbase,
        float* __restrict__ zsum, long long zbase, int emode) {
    uint32_t sbase = smem_u32(smem);
    int tid = threadIdx.x, lane = tid & 31, wid = tid >> 5;
    int g = lane >> 2, qid = lane & 3;
    int wm = (wid & 1) * 64, wn = (wid >> 1) * 32;

    A += (long long)m0 * Asm;
    B += (long long)n0 * Bsn;

    int row0 = tid >> 3, q0 = tid & 7;
    const __half* srcA = A + (long long)row0 * Asm + q0 * 8;
    const __half* srcB = B + (long long)row0 * Bsn + q0 * 8;
    uint32_t dstA = sbase + SWZ((uint32_t)(row0 * 128 + q0 * 16));

    float acc[4][4][4];
    #pragma unroll
    for (int i = 0; i < 4; i++)
        #pragma unroll
        for (int j = 0; j < 4; j++)
            #pragma unroll
            for (int qq = 0; qq < 4; qq++) acc[i][j][qq] = 0.f;

    int KB = K >> 6;

    #pragma unroll
    for (int s = 0; s < 2; s++) {
        uint32_t so = s * STAGEB;
        #pragma unroll
        for (int t = 0; t < 4; t++) {
            CPASYNC16(dstA + so + t * 4096,         srcA + s * 64 + (long long)(32 * t) * Asm);
            CPASYNC16(dstA + so + 16384 + t * 4096, srcB + s * 64 + (long long)(32 * t) * Bsn);
        }
        CP_COMMIT();
    }

    uint32_t baseA = (uint32_t)((wm + (lane & 15)) * 128 + (lane >> 4) * 16);
    uint32_t baseB = (uint32_t)((wn + (lane & 7) + ((lane >> 4) & 1) * 8) * 128 + ((lane >> 3) & 1) * 16);

    int st = 0;
    for (int kb = 0; kb < KB; kb++) {
        CP_WAIT1();
        __syncthreads();
        if (kb + 2 < KB) {
            int s2 = st + 2; if (s2 >= NSTAGE) s2 -= NSTAGE;
            uint32_t so = (uint32_t)s2 * STAGEB;
            #pragma unroll
            for (int t = 0; t < 4; t++) {
                CPASYNC16(dstA + so + t * 4096,         srcA + (kb + 2) * 64 + (long long)(32 * t) * Asm);
                CPASYNC16(dstA + so + 16384 + t * 4096, srcB + (kb + 2) * 64 + (long long)(32 * t) * Bsn);
            }
        }
        CP_COMMIT();

        uint32_t sA = sbase + st * STAGEB;
        uint32_t sB = sA + 16384;

        #pragma unroll
        for (int ks = 0; ks < 4; ks++) {
            uint32_t a[4][4], bf[2][4];
            #pragma unroll
            for (int mt = 0; mt < 4; mt++)
                LDSM4(a[mt][0], a[mt][1], a[mt][2], a[mt][3],
                      sA + SWZ(baseA + mt * 2048 + ks * 32));
            #pragma unroll
            for (int ntp = 0; ntp < 2; ntp++)
                LDSM4(bf[ntp][0], bf[ntp][1], bf[ntp][2], bf[ntp][3],
                      sB + SWZ(baseB + ntp * 2048 + ks * 32));
            #pragma unroll
            for (int mt = 0; mt < 4; mt++)
                #pragma unroll
                for (int nt = 0; nt < 4; nt++) {
                    uint32_t b0 = bf[nt >> 1][(nt & 1) * 2];
                    uint32_t b1 = bf[nt >> 1][(nt & 1) * 2 + 1];
                    HMMA16(acc[mt][nt], a[mt][0], a[mt][1], a[mt][2], a[mt][3], b0, b1);
                }
        }
        st++; if (st == NSTAGE) st = 0;
    }

    // ---------------- epilogue ----------------
    #pragma unroll
    for (int mt = 0; mt < 4; mt++) {
        int r = m0 + wm + 16 * mt + g;
        float bm0 = 0.f, bm1 = 0.f;
        if (bias_m) {
            if (bmode == 1) { bm0 = bias_m[qkv_map_m(r)]; bm1 = bias_m[qkv_map_m(r + 8)]; }
            else            { bm0 = bias_m[r]; bm1 = bias_m[r + 8]; }
        }
        float zs0 = 0.f, zs1 = 0.f;
        #pragma unroll
        for (int nt = 0; nt < 4; nt++) {
            float* c = acc[mt][nt];
            int n = n0 + wn + 8 * nt + qid * 2;
            long long o0 = cbase + (long long)r * Csm + n;
            long long o1 = cbase + (long long)(r + 8) * Csm + n;
            if (emode) {
                float e00 = __expf(c[0] * alpha - 2.0f);
                float e01 = __expf(c[1] * alpha - 2.0f);
                float e10 = __expf(c[2] * alpha - 2.0f);
                float e11 = __expf(c[3] * alpha - 2.0f);
                zs0 += e00 + e01; zs1 += e10 + e11;
                *(__half2*)((__half*)Cv + o0) = __floats2half2_rn(e00, e01);
                *(__half2*)((__half*)Cv + o1) = __floats2half2_rn(e10, e11);
                continue;
            }
            float bn0 = 0.f, bn1 = 0.f;
            if (bias_n) {
                if (bmode == 2) { bn0 = bias_n[qkv_map_v(n)]; bn1 = bias_n[qkv_map_v(n + 1)]; }
                else            { bn0 = bias_n[n]; bn1 = bias_n[n + 1]; }
            }
            float v00 = c[0] * alpha + bm0 + bn0;
            float v01 = c[1] * alpha + bm0 + bn1;
            float v10 = c[2] * alpha + bm1 + bn0;
            float v11 = c[3] * alpha + bm1 + bn1;
            if (rowscale) {
                float rs0 = 1.0f / rowscale[rsbase + n];
                float rs1 = 1.0f / rowscale[rsbase + n + 1];
                v00 *= rs0; v01 *= rs1; v10 *= rs0; v11 *= rs1;
            }
            if (c16) {
                *(__half2*)((__half*)Cv + o0) = __floats2half2_rn(v00, v01);
                *(__half2*)((__half*)Cv + o1) = __floats2half2_rn(v10, v11);
            } else {
                float* C = (float*)Cv;
                if (resid) {
                    v00 += resid[o0]; v01 += resid[o0 + 1];
                    v10 += resid[o1]; v11 += resid[o1 + 1];
                }
                *(float2*)(C + o0) = make_float2(v00, v01);
                *(float2*)(C + o1) = make_float2(v10, v11);
            }
        }
        if (emode) {
            zs0 += __shfl_xor_sync(0xffffffffu, zs0, 1);
            zs0 += __shfl_xor_sync(0xffffffffu, zs0, 2);
            zs1 += __shfl_xor_sync(0xffffffffu, zs1, 1);
            zs1 += __shfl_xor_sync(0xffffffffu, zs1, 2);
            if (qid == 0) {
                atomicAdd(&zsum[zbase + r], zs0);
                atomicAdd(&zsum[zbase + r + 8], zs1);
            }
        }
    }
}

// Q,K projection: 2048 blocks -> qkT[feat][bt]
__global__ void __launch_bounds__(256, 2)
hgemm_2a(const float* __restrict__ b_qkv) {
    extern __shared__ char smem[];
    int bx = blockIdx.x;
    gemm_body(smem, g_wqkT, g_h, g_qkT, NC,
              512, 512, BT, 0,
              (bx & 31) * 128, (bx >> 5) * 128,
              1.0f, b_qkv, nullptr, nullptr, 1, 1, nullptr, 0, nullptr, 0, 0);
}

// merged: blocks [0,512) = QK logits->E tiles; blocks [512,1536) = V projection
__global__ void __launch_bounds__(256, 2)
hgemm_qk_v(const float* __restrict__ b_qkv) {
    extern __shared__ char smem[];
    int bx = blockIdx.x;
    float* Zp;
    asm("cvta.global.u64 %0, %1;" : "=l"(Zp) : "l"(g_Z));
    if (bx < 512) {
        int z = bx >> 4;
        int zi = z & 3, zo = z >> 2;
        int m0 = ((bx >> 2) & 3) * 128;
        int n0 = (bx & 3) * 128;
        gemm_body(smem,
                  g_qkT + (long long)zi * 512 * BT + (long long)zo * NT,
                  g_qkT + 2048LL * BT + (long long)zi * 512 * BT + (long long)zo * NT,
                  g_attnh, NT,
                  BT, BT, NC,
                  (long long)z * NC * NC, m0, n0,
                  1.0f / 32.0f, nullptr, nullptr, nullptr, 1, 0,
                  nullptr, 0, Zp, (long long)z * 512, 1);
    } else {
        int j = bx - 512;
        gemm_body(smem, g_h, g_wqkT + 4096LL * 512, g_v2, NC,
                  512, 512, NF, 0,
                  (j >> 4) * 128, (j & 15) * 128,
                  1.0f, nullptr, b_qkv, nullptr, 1, 2, nullptr, 0, nullptr, 0, 0);
    }
}

// merged AV + Out with tile-granular dependency counters.
// blocks [0,1024): AV (z = bx>>5, t-tile = (bx>>2)&7, c-tile = bx&3)
// blocks [1024,1280): Out, waits for g_cnt[b*8+tt] == 16.
// Safety: 256 consumer CTAs < 296 slots -> producers always have slots.
__global__ void __launch_bounds__(256, 2)
hgemm_av_out(const float* __restrict__ b_out, const float* __restrict__ x,
             float* __restrict__ out) {
    extern __shared__ char smem[];
    int bx = blockIdx.x;
    int tid = threadIdx.x;
    float* Zp;
    asm("cvta.global.u64 %0, %1;" : "=l"(Zp) : "l"(g_Z));
    if (bx < 1024) {
        int z = bx >> 5;                   // b*4+h
        int zi = z & 3, zo = z >> 2;
        int tt = (bx >> 2) & 7, cc = bx & 3;
        gemm_body(smem,
                  g_v2 + zi * 512 + (long long)zo * NT * NF,
                  g_attnh + (long long)z * NC * NC,
                  g_av2, NC,
                  NF, NC, NF,
                  (long long)zi * 512 + (long long)zo * NT * NF,
                  tt * 128, cc * 128,
                  1.0f, nullptr, nullptr, nullptr, 1, 0,
                  Zp, (long long)z * 512, nullptr, 0, 0);
        __threadfence();
        __syncthreads();
        if (tid == 0) atomicAdd(&g_cnt[zo * 8 + tt], 1);
    } else {
        int j = bx - 1024;                 // 0..255
        int b = j >> 5, tt = (j >> 2) & 7, cc = j & 3;
        if (tid == 0) {
            while (atomicAdd(&g_cnt[b * 8 + tt], 0) < 16) { }
        }
        __syncthreads();
        gemm_body(smem, g_av2 + (long long)b * NT * NF, g_woutT, out, NF,
                  NF, NF, NC, (long long)b * NT * NC,
                  tt * 128, cc * 128,
                  1.0f, nullptr, b_out, x, 0, 0, nullptr, 0, nullptr, 0, 0);
    }
}

extern "C" void kernel_launch(void* const* d_in, const int* in_sizes, int n_in,
                              void* d_out, int out_size) {
    const float* x        = (const float*)d_in[0];
    const float* gn_scale = (const float*)d_in[1];
    const float* gn_bias  = (const float*)d_in[2];
    const float* w_qkv    = (const float*)d_in[3];
    const float* b_qkv    = (const float*)d_in[4];
    const float* w_out    = (const float*)d_in[5];
    const float* b_out    = (const float*)d_in[6];
    float* out = (float*)d_out;

    cudaFuncSetAttribute(hgemm_2a,     cudaFuncAttributeMaxDynamicSharedMemorySize, GSMEM);
    cudaFuncSetAttribute(hgemm_qk_v,   cudaFuncAttributeMaxDynamicSharedMemorySize, GSMEM);
    cudaFuncSetAttribute(hgemm_av_out, cudaFuncAttributeMaxDynamicSharedMemorySize, GSMEM);

    // 0: merged prep (groupnorm + transposes + Z/counter zero)
    gn_tr<<<1472, 256>>>(x, gn_scale, gn_bias, w_qkv, w_out);

    // 1: Q,K projection
    hgemm_2a<<<2048, 256, GSMEM>>>(b_qkv);

    // 2: QK logits -> E + Z atomics, co-scheduled with V projection
    hgemm_qk_v<<<1536, 256, GSMEM>>>(b_qkv);

    // 3: AV + Out merged with dependency counters
    hgemm_av_out<<<1280, 256, GSMEM>>>(b_out, x, out);
}